// round 10
// baseline (speedup 1.0000x reference)
#include <cuda_runtime.h>
#include <cuda_fp16.h>
#include <math.h>
#include <stdint.h>

// Problem constants
#define Bn   16
#define Cc   256
#define Nn   4096
#define Hh   4
#define Dd   64
#define O3   768
#define HID  256
#define SCALE 0.125f

// Scratch (all operands pre-split half pairs)
__device__ __half g_xh[(size_t)Bn * Cc * Nn];
__device__ __half g_xl[(size_t)Bn * Cc * Nn];
__device__ __half g_wh[O3 * Cc];
__device__ __half g_wl[O3 * Cc];
__device__ __half g_qh[(size_t)Bn * HID * Nn];
__device__ __half g_ql[(size_t)Bn * HID * Nn];
__device__ __half g_kh[(size_t)Bn * HID * Nn];
__device__ __half g_kl[(size_t)Bn * HID * Nn];
__device__ __half g_vh[(size_t)Bn * HID * Nn];
__device__ __half g_vl[(size_t)Bn * HID * Nn];
__device__ float  g_ctxp[(size_t)Bn * Hh * 16 * Dd * Dd];
__device__ __half g_w2h[(size_t)Bn * HID * HID];
__device__ __half g_w2l[(size_t)Bn * HID * HID];

// ===========================================================================
// Helpers
// ===========================================================================
__device__ __forceinline__ uint32_t smem_u32(const void* p) {
    uint32_t a;
    asm("{ .reg .u64 t; cvta.to.shared.u64 t, %1; cvt.u32.u64 %0, t; }" : "=r"(a) : "l"(p));
    return a;
}
__device__ __forceinline__ void split_h(float x, __half& h, __half& l) {
    h = __float2half_rn(x);
    l = __float2half_rn(x - __half2float(h));
}
__device__ __forceinline__ void mma16(float* d, const uint32_t* a, const uint32_t* b) {
    asm volatile(
        "mma.sync.aligned.m16n8k16.row.col.f32.f16.f16.f32 "
        "{%0,%1,%2,%3},{%4,%5,%6,%7},{%8,%9},{%0,%1,%2,%3};"
        : "+f"(d[0]), "+f"(d[1]), "+f"(d[2]), "+f"(d[3])
        : "r"(a[0]), "r"(a[1]), "r"(a[2]), "r"(a[3]), "r"(b[0]), "r"(b[1]));
}
#define LDM_X4(r, addr) \
    asm volatile("ldmatrix.sync.aligned.m8n8.x4.shared.b16 {%0,%1,%2,%3}, [%4];" \
        : "=r"((r)[0]), "=r"((r)[1]), "=r"((r)[2]), "=r"((r)[3]) : "r"(addr))
#define LDM_X4_T(r, addr) \
    asm volatile("ldmatrix.sync.aligned.m8n8.x4.trans.shared.b16 {%0,%1,%2,%3}, [%4];" \
        : "=r"((r)[0]), "=r"((r)[1]), "=r"((r)[2]), "=r"((r)[3]) : "r"(addr))
#define CP_ASYNC16(dst, src) \
    asm volatile("cp.async.cg.shared.global [%0], [%1], 16;" :: "r"(dst), "l"(src))
#define CP_COMMIT() asm volatile("cp.async.commit_group;" ::: "memory")
#define CP_WAIT(n)  asm volatile("cp.async.wait_group %0;" :: "n"(n) : "memory")

// ===========================================================================
__global__ void split_kernel(const float* __restrict__ src,
                             __half* __restrict__ h, __half* __restrict__ l, int n4)
{
    int i = blockIdx.x * blockDim.x + threadIdx.x;
    if (i >= n4) return;
    float4 v = *(const float4*)(src + (size_t)i * 4);
    __half h0, l0, h1, l1;
    split_h(v.x, h0, l0); split_h(v.y, h1, l1);
    *(half2*)(h + (size_t)i * 4)     = __halves2half2(h0, h1);
    *(half2*)(l + (size_t)i * 4)     = __halves2half2(l0, l1);
    split_h(v.z, h0, l0); split_h(v.w, h1, l1);
    *(half2*)(h + (size_t)i * 4 + 2) = __halves2half2(h0, h1);
    *(half2*)(l + (size_t)i * 4 + 2) = __halves2half2(l0, l1);
}

// ===========================================================================
// fused_gemm: 3-term fp16-split GEMM. Tile 128x128, BK=32, 8 slices,
// 2-stage cp.async double buffer => 75,776 B smem => 2 CTAs/SM resident.
// 8 warps = 2m x 4n (warp 64x32).
// sec: 0=q (fused softmax_d -> pairs), 1=k (pairs), 2=v (pairs),
//      3=fp32 out + bias (GEMM2).
// ===========================================================================
#define PA_B 80                      // A pitch bytes (32 halves + 16 pad)
#define PB_B 272                     // B pitch bytes (128 halves + 16 pad)
#define A_ST (128 * PA_B)            // 10240
#define B_ST (32 * PB_B)             // 8704
#define STG  (2 * A_ST + 2 * B_ST)   // 37888
#define FG_SMEM (2 * STG)            // 75776  -> two CTAs fit per SM

__global__ void __launch_bounds__(256, 2)
fused_gemm(const __half* __restrict__ Ah, const __half* __restrict__ Al, size_t aStride,
           const __half* __restrict__ Bh, const __half* __restrict__ Bl, size_t bStride,
           int sec, const float* __restrict__ bias, float* __restrict__ outF)
{
    extern __shared__ char smem[];
    const uint32_t sb = smem_u32(smem);
    const int tid  = threadIdx.x;
    const int wid  = tid >> 5;
    const int lane = tid & 31;
    const int wm   = (wid >> 2) * 64;
    const int wn   = (wid & 3) * 32;
    const int mBlk = blockIdx.y * 128;
    const int nBlk = blockIdx.x * 128;
    const int z    = blockIdx.z;

    const __half* Agh = Ah + (size_t)z * aStride + (size_t)mBlk * 256;
    const __half* Agl = Al + (size_t)z * aStride + (size_t)mBlk * 256;
    const __half* Bgh = Bh + (size_t)z * bStride + nBlk;
    const __half* Bgl = Bl + (size_t)z * bStride + nBlk;

    float acc[4][4][4];
    #pragma unroll
    for (int i = 0; i < 4; i++)
        #pragma unroll
        for (int j = 0; j < 4; j++)
            #pragma unroll
            for (int r = 0; r < 4; r++) acc[i][j][r] = 0.f;

    auto issue = [&](int s, int buf) {
        const int kk = s * 32;
        const uint32_t st = sb + buf * STG;
        #pragma unroll
        for (int p = 0; p < 2; p++) {            // A: 128 rows x 4 chunks x2
            int id = tid + p * 256;
            int m = id >> 2, ch = id & 3;
            size_t go = (size_t)m * 256 + kk + ch * 8;
            uint32_t dst = st + m * PA_B + ch * 16;
            CP_ASYNC16(dst, Agh + go);
            CP_ASYNC16(dst + A_ST, Agl + go);
        }
        #pragma unroll
        for (int p = 0; p < 2; p++) {            // B: 32 rows x 16 chunks x2
            int id = tid + p * 256;
            int r = id >> 4, ch = id & 15;
            size_t go = (size_t)(kk + r) * Nn + ch * 8;
            uint32_t dst = st + 2 * A_ST + r * PB_B + ch * 16;
            CP_ASYNC16(dst, Bgh + go);
            CP_ASYNC16(dst + B_ST, Bgl + go);
        }
    };

    const int lr = lane & 15;
    const int lc = (lane >> 4) & 1;

    auto compute = [&](int buf) {
        const uint32_t aHb = sb + buf * STG;
        const uint32_t aLb = aHb + A_ST;
        const uint32_t bHb = aLb + A_ST;
        const uint32_t bLb = bHb + B_ST;
        #pragma unroll
        for (int ks = 0; ks < 2; ks++) {
            uint32_t bh[2][4], bl[2][4];
            #pragma unroll
            for (int fnp = 0; fnp < 2; fnp++) {
                uint32_t off = (uint32_t)(ks * 16 + lr) * PB_B
                             + (uint32_t)(wn + fnp * 16 + lc * 8) * 2;
                LDM_X4_T(bh[fnp], bHb + off);
                LDM_X4_T(bl[fnp], bLb + off);
            }
            #pragma unroll
            for (int fm = 0; fm < 4; fm++) {
                uint32_t off = (uint32_t)(wm + fm * 16 + lr) * PA_B
                             + (uint32_t)(ks * 16 + lc * 8) * 2;
                uint32_t ah[4], al[4];
                LDM_X4(ah, aHb + off);
                LDM_X4(al, aLb + off);
                #pragma unroll
                for (int fn = 0; fn < 4; fn++)
                    mma16(acc[fm][fn], ah, &bh[fn >> 1][(fn & 1) * 2]);
                #pragma unroll
                for (int fn = 0; fn < 4; fn++)
                    mma16(acc[fm][fn], ah, &bl[fn >> 1][(fn & 1) * 2]);
                #pragma unroll
                for (int fn = 0; fn < 4; fn++)
                    mma16(acc[fm][fn], al, &bh[fn >> 1][(fn & 1) * 2]);
            }
        }
    };

    issue(0, 0); CP_COMMIT();
    issue(1, 1); CP_COMMIT();
    #pragma unroll 1
    for (int s = 0; s < 8; s++) {
        if (s < 7) { CP_WAIT(1); } else { CP_WAIT(0); }
        __syncthreads();
        compute(s & 1);
        if (s + 2 < 8) {
            __syncthreads();                  // all warps done reading buf s&1
            issue(s + 2, s & 1); CP_COMMIT();
        }
    }

    // ------------------------------ epilogues ------------------------------
    if (sec == 3) {
        float* Cg = outF + (size_t)z * HID * Nn;
        #pragma unroll
        for (int fm = 0; fm < 4; fm++) {
            int row = mBlk + wm + fm * 16 + (lane >> 2);
            float b0 = bias[row], b8 = bias[row + 8];
            #pragma unroll
            for (int fn = 0; fn < 4; fn++) {
                int col = nBlk + wn + fn * 8 + (lane & 3) * 2;
                float2 v0 = { acc[fm][fn][0] + b0, acc[fm][fn][1] + b0 };
                float2 v1 = { acc[fm][fn][2] + b8, acc[fm][fn][3] + b8 };
                *(float2*)&Cg[(size_t)row * Nn + col]       = v0;
                *(float2*)&Cg[(size_t)(row + 8) * Nn + col] = v1;
            }
        }
        return;
    }

    if (sec != 0) {    // K or V: half pairs
        __half* Oh = (sec == 1 ? g_kh : g_vh) + ((size_t)z * HID + mBlk) * Nn;
        __half* Ol = (sec == 1 ? g_kl : g_vl) + ((size_t)z * HID + mBlk) * Nn;
        #pragma unroll
        for (int fm = 0; fm < 4; fm++) {
            int row = wm + fm * 16 + (lane >> 2);
            #pragma unroll
            for (int fn = 0; fn < 4; fn++) {
                int col = nBlk + wn + fn * 8 + (lane & 3) * 2;
                __half h0, l0, h1, l1;
                split_h(acc[fm][fn][0], h0, l0); split_h(acc[fm][fn][1], h1, l1);
                *(half2*)&Oh[(size_t)row * Nn + col] = __halves2half2(h0, h1);
                *(half2*)&Ol[(size_t)row * Nn + col] = __halves2half2(l0, l1);
                split_h(acc[fm][fn][2], h0, l0); split_h(acc[fm][fn][3], h1, l1);
                *(half2*)&Oh[(size_t)(row + 8) * Nn + col] = __halves2half2(h0, h1);
                *(half2*)&Ol[(size_t)(row + 8) * Nn + col] = __halves2half2(l0, l1);
            }
        }
        return;
    }

    // Q: fused softmax over d (2 heads per 128-row tile), x SCALE
    {
        float* S    = (float*)smem;                       // [128][132] = 67584 B
        float* cInv = (float*)(smem + 128 * 132 * 4);     // [256]
        __syncthreads();
        #pragma unroll
        for (int fm = 0; fm < 4; fm++) {
            int row = wm + fm * 16 + (lane >> 2);
            #pragma unroll
            for (int fn = 0; fn < 4; fn++) {
                int col = wn + fn * 8 + (lane & 3) * 2;
                *(float2*)&S[row * 132 + col]       = make_float2(acc[fm][fn][0], acc[fm][fn][1]);
                *(float2*)&S[(row + 8) * 132 + col] = make_float2(acc[fm][fn][2], acc[fm][fn][3]);
            }
        }
        __syncthreads();

        {
            int colI = tid & 127;
            int hf   = tid >> 7;
            float mx = -INFINITY;
            #pragma unroll 4
            for (int r = 0; r < 64; r++)
                mx = fmaxf(mx, S[(hf * 64 + r) * 132 + colI]);
            float sum = 0.f;
            #pragma unroll 4
            for (int r = 0; r < 64; r++) {
                float e = __expf(S[(hf * 64 + r) * 132 + colI] - mx);
                S[(hf * 64 + r) * 132 + colI] = e;
                sum += e;
            }
            cInv[tid] = SCALE / sum;
        }
        __syncthreads();

        __half* Qh = g_qh + ((size_t)z * HID + mBlk) * Nn + nBlk;
        __half* Ql = g_ql + ((size_t)z * HID + mBlk) * Nn + nBlk;
        int c2   = (tid & 63) * 2;
        int rgrp = tid >> 6;
        #pragma unroll 4
        for (int rr = 0; rr < 32; rr++) {
            int row = rgrp * 32 + rr;
            int ci  = ((row >> 6) << 7) | c2;
            float2 v = *(float2*)&S[row * 132 + c2];
            float e0 = v.x * cInv[ci];
            float e1 = v.y * cInv[ci + 1];
            __half h0, l0, h1, l1;
            split_h(e0, h0, l0); split_h(e1, h1, l1);
            *(half2*)&Qh[(size_t)row * Nn + c2] = __halves2half2(h0, h1);
            *(half2*)&Ql[(size_t)row * Nn + c2] = __halves2half2(l0, l1);
        }
    }
}

// ===========================================================================
// Softmax over n on k: half pairs in/out. One block per (b,hd) row.
// ===========================================================================
__global__ void softmax_k_kernel()
{
    int row = blockIdx.x;
    size_t base = (size_t)row * Nn;
    __shared__ float red[256];
    const int tid = threadIdx.x;
    float v[16];
    float mx = -INFINITY;
    #pragma unroll
    for (int i = 0; i < 16; i++) {
        v[i] = __half2float(g_kh[base + tid + i * 256])
             + __half2float(g_kl[base + tid + i * 256]);
        mx = fmaxf(mx, v[i]);
    }
    red[tid] = mx; __syncthreads();
    for (int s = 128; s > 0; s >>= 1) { if (tid < s) red[tid] = fmaxf(red[tid], red[tid + s]); __syncthreads(); }
    mx = red[0]; __syncthreads();
    float sum = 0.f;
    #pragma unroll
    for (int i = 0; i < 16; i++) { v[i] = __expf(v[i] - mx); sum += v[i]; }
    red[tid] = sum; __syncthreads();
    for (int s = 128; s > 0; s >>= 1) { if (tid < s) red[tid] += red[tid + s]; __syncthreads(); }
    float inv = 1.f / red[0];
    #pragma unroll
    for (int i = 0; i < 16; i++) {
        __half hh, ll;
        split_h(v[i] * inv, hh, ll);
        g_kh[base + tid + i * 256] = hh;
        g_kl[base + tid + i * 256] = ll;
    }
}

// ===========================================================================
// Context partials (16 n-chunks of 256): ctxp[bh][p][d][e] = sum k[d,n]v[e,n]
// ===========================================================================
#define PK_B 272
#define CT_B (64 * PK_B)
#define CTX_SMEM_BYTES (4 * CT_B)

__global__ void __launch_bounds__(128, 2)
context_part()
{
    extern __shared__ char smem[];
    const uint32_t sb = smem_u32(smem);
    int bh = blockIdx.x;
    int p  = blockIdx.y;
    int b = bh >> 2, h = bh & 3;
    const __half* Kh = g_kh + ((size_t)b * HID + h * Dd) * Nn;
    const __half* Kl = g_kl + ((size_t)b * HID + h * Dd) * Nn;
    const __half* Vh = g_vh + ((size_t)b * HID + h * Dd) * Nn;
    const __half* Vl = g_vl + ((size_t)b * HID + h * Dd) * Nn;

    const int tid  = threadIdx.x;
    const int wid  = tid >> 5;
    const int lane = tid & 31;
    const int wm = (wid >> 1) * 32;
    const int wn = (wid & 1) * 32;

    float acc[2][4][4];
    #pragma unroll
    for (int i = 0; i < 2; i++)
        #pragma unroll
        for (int j = 0; j < 4; j++)
            #pragma unroll
            for (int r = 0; r < 4; r++) acc[i][j][r] = 0.f;

    const int lr = lane & 15;
    const int lc = (lane >> 4) & 1;
    const uint32_t kHb = sb;
    const uint32_t kLb = kHb + CT_B;
    const uint32_t vHb = kLb + CT_B;
    const uint32_t vLb = vHb + CT_B;

    #pragma unroll 1
    for (int sl = 0; sl < 2; sl++) {
        const int nn = p * 256 + sl * 128;
        __syncthreads();
        #pragma unroll
        for (int q = 0; q < 8; q++) {
            int id = tid + q * 128;
            int row = id >> 4, ch = id & 15;
            size_t go = (size_t)row * Nn + nn + ch * 8;
            uint32_t off = row * PK_B + ch * 16;
            CP_ASYNC16(kHb + off, Kh + go);
            CP_ASYNC16(kLb + off, Kl + go);
            CP_ASYNC16(vHb + off, Vh + go);
            CP_ASYNC16(vLb + off, Vl + go);
        }
        CP_COMMIT();
        CP_WAIT(0);
        __syncthreads();

        #pragma unroll
        for (int ks = 0; ks < 8; ks++) {
            uint32_t bhf[2][4], blf[2][4];
            #pragma unroll
            for (int fnp = 0; fnp < 2; fnp++) {
                uint32_t off = (uint32_t)(wn + fnp * 16 + lc * 8 + (lane & 7)) * PK_B
                             + (uint32_t)(ks * 32 + ((lane >> 3) & 1) * 16);
                LDM_X4(bhf[fnp], vHb + off);
                LDM_X4(blf[fnp], vLb + off);
            }
            #pragma unroll
            for (int fm = 0; fm < 2; fm++) {
                uint32_t off = (uint32_t)(wm + fm * 16 + lr) * PK_B
                             + (uint32_t)(ks * 32 + lc * 16);
                uint32_t ah[4], al[4];
                LDM_X4(ah, kHb + off);
                LDM_X4(al, kLb + off);
                #pragma unroll
                for (int fn = 0; fn < 4; fn++)
                    mma16(acc[fm][fn], ah, &bhf[fn >> 1][(fn & 1) * 2]);
                #pragma unroll
                for (int fn = 0; fn < 4; fn++)
                    mma16(acc[fm][fn], ah, &blf[fn >> 1][(fn & 1) * 2]);
                #pragma unroll
                for (int fn = 0; fn < 4; fn++)
                    mma16(acc[fm][fn], al, &bhf[fn >> 1][(fn & 1) * 2]);
            }
        }
    }

    float* dst = g_ctxp + ((size_t)bh * 16 + p) * (Dd * Dd);
    #pragma unroll
    for (int fm = 0; fm < 2; fm++) {
        int d0 = wm + fm * 16 + (lane >> 2);
        #pragma unroll
        for (int fn = 0; fn < 4; fn++) {
            int e0 = wn + fn * 8 + (lane & 3) * 2;
            dst[d0 * Dd + e0]           = acc[fm][fn][0];
            dst[d0 * Dd + e0 + 1]       = acc[fm][fn][1];
            dst[(d0 + 8) * Dd + e0]     = acc[fm][fn][2];
            dst[(d0 + 8) * Dd + e0 + 1] = acc[fm][fn][3];
        }
    }
}

// ===========================================================================
// W2[b][c][h*64+d] = sum_e w_out[c][h*64+e] * ctx[bh][d][e]; half pairs out.
// ===========================================================================
__global__ void w2_kernel(const float* __restrict__ w_out)
{
    int bh = blockIdx.x;
    int b = bh >> 2, h = bh & 3;
    __shared__ float ctx[Dd * Dd];
    const int tid = threadIdx.x;

    for (int i = tid; i < Dd * Dd; i += 256) {
        float s = 0.f;
        #pragma unroll
        for (int p = 0; p < 16; p++)
            s += g_ctxp[((size_t)bh * 16 + p) * (Dd * Dd) + i];
        ctx[i] = s;
    }
    __syncthreads();

    int c = tid;
    float w[Dd];
    #pragma unroll
    for (int e = 0; e < Dd; e++) w[e] = w_out[c * HID + h * Dd + e];
    #pragma unroll 4
    for (int d = 0; d < Dd; d++) {
        float s = 0.f;
        #pragma unroll
        for (int e = 0; e < Dd; e++) s = fmaf(w[e], ctx[d * Dd + e], s);
        __half hh, ll;
        split_h(s, hh, ll);
        size_t o = ((size_t)b * HID + c) * HID + h * Dd + d;
        g_w2h[o] = hh;
        g_w2l[o] = ll;
    }
}

// ===========================================================================
extern "C" void kernel_launch(void* const* d_in, const int* in_sizes, int n_in,
                              void* d_out, int out_size)
{
    const float* x     = (const float*)d_in[0];
    const float* w_qkv = (const float*)d_in[1];
    const float* w_out = (const float*)d_in[2];
    const float* b_out = (const float*)d_in[3];
    float* out = (float*)d_out;

    __half *xh, *xl, *wh, *wl, *qh, *ql, *w2h, *w2l;
    cudaGetSymbolAddress((void**)&xh, g_xh);
    cudaGetSymbolAddress((void**)&xl, g_xl);
    cudaGetSymbolAddress((void**)&wh, g_wh);
    cudaGetSymbolAddress((void**)&wl, g_wl);
    cudaGetSymbolAddress((void**)&qh, g_qh);
    cudaGetSymbolAddress((void**)&ql, g_ql);
    cudaGetSymbolAddress((void**)&w2h, g_w2h);
    cudaGetSymbolAddress((void**)&w2l, g_w2l);

    static int init_done = 0;
    static cudaStream_t s2;
    static cudaEvent_t evK, evV, evW2;
    if (!init_done) {
        cudaFuncSetAttribute(fused_gemm, cudaFuncAttributeMaxDynamicSharedMemorySize, FG_SMEM);
        cudaFuncSetAttribute(context_part, cudaFuncAttributeMaxDynamicSharedMemorySize, CTX_SMEM_BYTES);
        cudaStreamCreateWithFlags(&s2, cudaStreamNonBlocking);
        cudaEventCreateWithFlags(&evK, cudaEventDisableTiming);
        cudaEventCreateWithFlags(&evV, cudaEventDisableTiming);
        cudaEventCreateWithFlags(&evW2, cudaEventDisableTiming);
        init_done = 1;
    }

    // 0) pre-split x and w_qkv (main stream)
    {
        int n4 = (Bn * Cc * Nn) / 4;
        split_kernel<<<(n4 + 255) / 256, 256>>>(x, xh, xl, n4);
        int w4 = (O3 * Cc) / 4;
        split_kernel<<<(w4 + 255) / 256, 256>>>(w_qkv, wh, wl, w4);
    }

    dim3 grid1(Nn / 128, 2, Bn);   // per-section GEMM1 grids (256 rows each)

    // 1a) GEMM1 K section
    fused_gemm<<<grid1, 256, FG_SMEM>>>(wh + (size_t)256 * Cc, wl + (size_t)256 * Cc, 0,
                                        xh, xl, (size_t)Cc * Nn, 1, nullptr, nullptr);
    cudaEventRecord(evK, 0);

    // 1b) GEMM1 V section (overlaps softmax_k on s2)
    fused_gemm<<<grid1, 256, FG_SMEM>>>(wh + (size_t)512 * Cc, wl + (size_t)512 * Cc, 0,
                                        xh, xl, (size_t)Cc * Nn, 2, nullptr, nullptr);
    cudaEventRecord(evV, 0);

    // side stream: softmax_k after K, then context+w2 after V
    cudaStreamWaitEvent(s2, evK, 0);
    softmax_k_kernel<<<Bn * HID, 256, 0, s2>>>();
    cudaStreamWaitEvent(s2, evV, 0);
    {
        dim3 gridc(Bn * Hh, 16);
        context_part<<<gridc, 128, CTX_SMEM_BYTES, s2>>>();
    }
    w2_kernel<<<Bn * Hh, 256, 0, s2>>>(w_out);
    cudaEventRecord(evW2, s2);

    // 1c) GEMM1 Q section (overlaps context/w2)
    fused_gemm<<<grid1, 256, FG_SMEM>>>(wh, wl, 0,
                                        xh, xl, (size_t)Cc * Nn, 0, nullptr, nullptr);

    // 2) GEMM2 after q and w2
    cudaStreamWaitEvent(0, evW2, 0);
    {
        dim3 grid2(Nn / 128, HID / 128, Bn);
        fused_gemm<<<grid2, 256, FG_SMEM>>>(w2h, w2l, (size_t)HID * HID,
                                            qh, ql, (size_t)HID * Nn, 3, b_out, out);
    }
}

// round 11
// speedup vs baseline: 1.2267x; 1.2267x over previous
#include <cuda_runtime.h>
#include <cuda_fp16.h>
#include <math.h>
#include <stdint.h>

// Problem constants
#define Bn   16
#define Cc   256
#define Nn   4096
#define Hh   4
#define Dd   64
#define O3   768
#define HID  256
#define SCALE 0.125f

// Scratch
__device__ __half g_xh[(size_t)Bn * Cc * Nn];     // x as fp16 (B operand, truncated)
__device__ __half g_wh[O3 * Cc];                  // w_qkv hi
__device__ __half g_wl[O3 * Cc];                  // w_qkv lo
__device__ __half g_qh[(size_t)Bn * HID * Nn];    // q softmaxed (fp16 only)
__device__ __half g_kh[(size_t)Bn * HID * Nn];    // k pairs (context needs precision)
__device__ __half g_kl[(size_t)Bn * HID * Nn];
__device__ __half g_vh[(size_t)Bn * HID * Nn];
__device__ __half g_vl[(size_t)Bn * HID * Nn];
__device__ float  g_ctxp[(size_t)Bn * Hh * 16 * Dd * Dd];
__device__ __half g_w2h[(size_t)Bn * HID * HID];
__device__ __half g_w2l[(size_t)Bn * HID * HID];

// ===========================================================================
// Helpers
// ===========================================================================
__device__ __forceinline__ uint32_t smem_u32(const void* p) {
    uint32_t a;
    asm("{ .reg .u64 t; cvta.to.shared.u64 t, %1; cvt.u32.u64 %0, t; }" : "=r"(a) : "l"(p));
    return a;
}
__device__ __forceinline__ void split_h(float x, __half& h, __half& l) {
    h = __float2half_rn(x);
    l = __float2half_rn(x - __half2float(h));
}
__device__ __forceinline__ void mma16(float* d, const uint32_t* a, const uint32_t* b) {
    asm volatile(
        "mma.sync.aligned.m16n8k16.row.col.f32.f16.f16.f32 "
        "{%0,%1,%2,%3},{%4,%5,%6,%7},{%8,%9},{%0,%1,%2,%3};"
        : "+f"(d[0]), "+f"(d[1]), "+f"(d[2]), "+f"(d[3])
        : "r"(a[0]), "r"(a[1]), "r"(a[2]), "r"(a[3]), "r"(b[0]), "r"(b[1]));
}
#define LDM_X4(r, addr) \
    asm volatile("ldmatrix.sync.aligned.m8n8.x4.shared.b16 {%0,%1,%2,%3}, [%4];" \
        : "=r"((r)[0]), "=r"((r)[1]), "=r"((r)[2]), "=r"((r)[3]) : "r"(addr))
#define LDM_X4_T(r, addr) \
    asm volatile("ldmatrix.sync.aligned.m8n8.x4.trans.shared.b16 {%0,%1,%2,%3}, [%4];" \
        : "=r"((r)[0]), "=r"((r)[1]), "=r"((r)[2]), "=r"((r)[3]) : "r"(addr))
#define CP_ASYNC16(dst, src) \
    asm volatile("cp.async.cg.shared.global [%0], [%1], 16;" :: "r"(dst), "l"(src))
#define CP_COMMIT() asm volatile("cp.async.commit_group;" ::: "memory")
#define CP_WAIT(n)  asm volatile("cp.async.wait_group %0;" :: "n"(n) : "memory")

// ===========================================================================
// Conversion kernels
// ===========================================================================
__global__ void half_kernel(const float* __restrict__ src, __half* __restrict__ h, int n4)
{
    int i = blockIdx.x * blockDim.x + threadIdx.x;
    if (i >= n4) return;
    float4 v = *(const float4*)(src + (size_t)i * 4);
    *(half2*)(h + (size_t)i * 4)     = __halves2half2(__float2half_rn(v.x), __float2half_rn(v.y));
    *(half2*)(h + (size_t)i * 4 + 2) = __halves2half2(__float2half_rn(v.z), __float2half_rn(v.w));
}

__global__ void split_kernel(const float* __restrict__ src,
                             __half* __restrict__ h, __half* __restrict__ l, int n4)
{
    int i = blockIdx.x * blockDim.x + threadIdx.x;
    if (i >= n4) return;
    float4 v = *(const float4*)(src + (size_t)i * 4);
    __half h0, l0, h1, l1;
    split_h(v.x, h0, l0); split_h(v.y, h1, l1);
    *(half2*)(h + (size_t)i * 4)     = __halves2half2(h0, h1);
    *(half2*)(l + (size_t)i * 4)     = __halves2half2(l0, l1);
    split_h(v.z, h0, l0); split_h(v.w, h1, l1);
    *(half2*)(h + (size_t)i * 4 + 2) = __halves2half2(h0, h1);
    *(half2*)(l + (size_t)i * 4 + 2) = __halves2half2(l0, l1);
}

// ===========================================================================
// fused_gemm: 2-term fp16-split GEMM (A = hi+lo pair, B = fp16).
// C = A x B, K=256, BK=64 (4 slices), 2-stage cp.async, 2 CTAs/SM.
// Tile 128x128, 8 warps = 2m x 4n (warp 64x32).
// mode 0 (GEMM1): blockIdx.y selects q(0-1, fused softmax_d -> fp16),
//                 k(2-3, pairs), v(4-5, pairs).
// mode 1 (GEMM2): fp32 out + bias.
// ===========================================================================
#define PA_B 144                     // A pitch bytes (64 halves + 16 pad)
#define PB_B 272                     // B pitch bytes (128 halves + 16 pad)
#define A_ST (128 * PA_B)            // 18432
#define B_ST (64 * PB_B)             // 17408
#define STG  (2 * A_ST + B_ST)       // 54272 (Ah, Al, Bh)
#define FG_SMEM (2 * STG)            // 108544 -> 2 CTAs/SM (217 KB)

__global__ void __launch_bounds__(256, 2)
fused_gemm(const __half* __restrict__ Ah, const __half* __restrict__ Al, size_t aStride,
           const __half* __restrict__ Bh, size_t bStride,
           int mode, const float* __restrict__ bias, float* __restrict__ outF)
{
    extern __shared__ char smem[];
    const uint32_t sb = smem_u32(smem);
    const int tid  = threadIdx.x;
    const int wid  = tid >> 5;
    const int lane = tid & 31;
    const int wm   = (wid >> 2) * 64;
    const int wn   = (wid & 3) * 32;
    const int mBlk = blockIdx.y * 128;
    const int nBlk = blockIdx.x * 128;
    const int z    = blockIdx.z;

    const __half* Agh = Ah + (size_t)z * aStride + (size_t)mBlk * 256;
    const __half* Agl = Al + (size_t)z * aStride + (size_t)mBlk * 256;
    const __half* Bg  = Bh + (size_t)z * bStride + nBlk;

    float acc[4][4][4];
    #pragma unroll
    for (int i = 0; i < 4; i++)
        #pragma unroll
        for (int j = 0; j < 4; j++)
            #pragma unroll
            for (int r = 0; r < 4; r++) acc[i][j][r] = 0.f;

    auto issue = [&](int s, int buf) {
        const int kk = s * 64;
        const uint32_t st = sb + buf * STG;
        #pragma unroll
        for (int p = 0; p < 4; p++) {            // A: 128 rows x 8 chunks, hi+lo
            int id = tid + p * 256;
            int m = id >> 3, ch = id & 7;
            size_t go = (size_t)m * 256 + kk + ch * 8;
            uint32_t dst = st + m * PA_B + ch * 16;
            CP_ASYNC16(dst, Agh + go);
            CP_ASYNC16(dst + A_ST, Agl + go);
        }
        #pragma unroll
        for (int p = 0; p < 4; p++) {            // B: 64 rows x 16 chunks
            int id = tid + p * 256;
            int r = id >> 4, ch = id & 15;
            size_t go = (size_t)(kk + r) * Nn + ch * 8;
            CP_ASYNC16(st + 2 * A_ST + r * PB_B + ch * 16, Bg + go);
        }
    };

    const int lr = lane & 15;
    const int lc = (lane >> 4) & 1;

    auto compute = [&](int buf) {
        const uint32_t aHb = sb + buf * STG;
        const uint32_t aLb = aHb + A_ST;
        const uint32_t bHb = aLb + A_ST;
        #pragma unroll
        for (int ks = 0; ks < 4; ks++) {
            uint32_t bh[2][4];
            #pragma unroll
            for (int fnp = 0; fnp < 2; fnp++) {
                uint32_t off = (uint32_t)(ks * 16 + lr) * PB_B
                             + (uint32_t)(wn + fnp * 16 + lc * 8) * 2;
                LDM_X4_T(bh[fnp], bHb + off);
            }
            #pragma unroll
            for (int fm = 0; fm < 4; fm++) {
                uint32_t off = (uint32_t)(wm + fm * 16 + lr) * PA_B
                             + (uint32_t)(ks * 16 + lc * 8) * 2;
                uint32_t ah[4], al[4];
                LDM_X4(ah, aHb + off);
                LDM_X4(al, aLb + off);
                #pragma unroll
                for (int fn = 0; fn < 4; fn++)
                    mma16(acc[fm][fn], ah, &bh[fn >> 1][(fn & 1) * 2]);
                #pragma unroll
                for (int fn = 0; fn < 4; fn++)
                    mma16(acc[fm][fn], al, &bh[fn >> 1][(fn & 1) * 2]);
            }
        }
    };

    issue(0, 0); CP_COMMIT();
    issue(1, 1); CP_COMMIT();
    #pragma unroll 1
    for (int s = 0; s < 4; s++) {
        if (s < 3) { CP_WAIT(1); } else { CP_WAIT(0); }
        __syncthreads();
        compute(s & 1);
        if (s + 2 < 4) {
            __syncthreads();
            issue(s + 2, s & 1); CP_COMMIT();
        }
    }

    // ------------------------------ epilogues ------------------------------
    if (mode == 1) {
        float* Cg = outF + (size_t)z * HID * Nn;
        #pragma unroll
        for (int fm = 0; fm < 4; fm++) {
            int row = mBlk + wm + fm * 16 + (lane >> 2);
            float b0 = bias[row], b8 = bias[row + 8];
            #pragma unroll
            for (int fn = 0; fn < 4; fn++) {
                int col = nBlk + wn + fn * 8 + (lane & 3) * 2;
                float2 v0 = { acc[fm][fn][0] + b0, acc[fm][fn][1] + b0 };
                float2 v1 = { acc[fm][fn][2] + b8, acc[fm][fn][3] + b8 };
                *(float2*)&Cg[(size_t)row * Nn + col]       = v0;
                *(float2*)&Cg[(size_t)(row + 8) * Nn + col] = v1;
            }
        }
        return;
    }

    const int y = blockIdx.y;
    if (y >= 2) {    // K or V: half pairs (context keeps 3-term precision)
        __half* Oh = (y < 4 ? g_kh : g_vh) + ((size_t)z * HID + mBlk - (y < 4 ? 256 : 512)) * Nn;
        __half* Ol = (y < 4 ? g_kl : g_vl) + ((size_t)z * HID + mBlk - (y < 4 ? 256 : 512)) * Nn;
        #pragma unroll
        for (int fm = 0; fm < 4; fm++) {
            int row = wm + fm * 16 + (lane >> 2);
            #pragma unroll
            for (int fn = 0; fn < 4; fn++) {
                int col = nBlk + wn + fn * 8 + (lane & 3) * 2;
                __half h0, l0, h1, l1;
                split_h(acc[fm][fn][0], h0, l0); split_h(acc[fm][fn][1], h1, l1);
                *(half2*)&Oh[(size_t)row * Nn + col] = __halves2half2(h0, h1);
                *(half2*)&Ol[(size_t)row * Nn + col] = __halves2half2(l0, l1);
                split_h(acc[fm][fn][2], h0, l0); split_h(acc[fm][fn][3], h1, l1);
                *(half2*)&Oh[(size_t)(row + 8) * Nn + col] = __halves2half2(h0, h1);
                *(half2*)&Ol[(size_t)(row + 8) * Nn + col] = __halves2half2(l0, l1);
            }
        }
        return;
    }

    // Q: fused softmax over d (2 heads per 128-row tile), x SCALE, fp16 out
    {
        float* S    = (float*)smem;                       // [128][132]
        float* cInv = (float*)(smem + 128 * 132 * 4);     // [256]
        __syncthreads();
        #pragma unroll
        for (int fm = 0; fm < 4; fm++) {
            int row = wm + fm * 16 + (lane >> 2);
            #pragma unroll
            for (int fn = 0; fn < 4; fn++) {
                int col = wn + fn * 8 + (lane & 3) * 2;
                *(float2*)&S[row * 132 + col]       = make_float2(acc[fm][fn][0], acc[fm][fn][1]);
                *(float2*)&S[(row + 8) * 132 + col] = make_float2(acc[fm][fn][2], acc[fm][fn][3]);
            }
        }
        __syncthreads();

        {
            int colI = tid & 127;
            int hf   = tid >> 7;
            float mx = -INFINITY;
            #pragma unroll 4
            for (int r = 0; r < 64; r++)
                mx = fmaxf(mx, S[(hf * 64 + r) * 132 + colI]);
            float sum = 0.f;
            #pragma unroll 4
            for (int r = 0; r < 64; r++) {
                float e = __expf(S[(hf * 64 + r) * 132 + colI] - mx);
                S[(hf * 64 + r) * 132 + colI] = e;
                sum += e;
            }
            cInv[tid] = SCALE / sum;
        }
        __syncthreads();

        __half* Qh = g_qh + ((size_t)z * HID + mBlk) * Nn + nBlk;
        int c2   = (tid & 63) * 2;
        int rgrp = tid >> 6;
        #pragma unroll 4
        for (int rr = 0; rr < 32; rr++) {
            int row = rgrp * 32 + rr;
            int ci  = ((row >> 6) << 7) | c2;
            float2 v = *(float2*)&S[row * 132 + c2];
            *(half2*)&Qh[(size_t)row * Nn + c2] =
                __halves2half2(__float2half_rn(v.x * cInv[ci]),
                               __float2half_rn(v.y * cInv[ci + 1]));
        }
    }
}

// ===========================================================================
// Softmax over n on k: half pairs in/out. One block per (b,hd) row.
// ===========================================================================
__global__ void softmax_k_kernel()
{
    int row = blockIdx.x;
    size_t base = (size_t)row * Nn;
    __shared__ float red[256];
    const int tid = threadIdx.x;
    float v[16];
    float mx = -INFINITY;
    #pragma unroll
    for (int i = 0; i < 16; i++) {
        v[i] = __half2float(g_kh[base + tid + i * 256])
             + __half2float(g_kl[base + tid + i * 256]);
        mx = fmaxf(mx, v[i]);
    }
    red[tid] = mx; __syncthreads();
    for (int s = 128; s > 0; s >>= 1) { if (tid < s) red[tid] = fmaxf(red[tid], red[tid + s]); __syncthreads(); }
    mx = red[0]; __syncthreads();
    float sum = 0.f;
    #pragma unroll
    for (int i = 0; i < 16; i++) { v[i] = __expf(v[i] - mx); sum += v[i]; }
    red[tid] = sum; __syncthreads();
    for (int s = 128; s > 0; s >>= 1) { if (tid < s) red[tid] += red[tid + s]; __syncthreads(); }
    float inv = 1.f / red[0];
    #pragma unroll
    for (int i = 0; i < 16; i++) {
        __half hh, ll;
        split_h(v[i] * inv, hh, ll);
        g_kh[base + tid + i * 256] = hh;
        g_kl[base + tid + i * 256] = ll;
    }
}

// ===========================================================================
// Context partials (16 n-chunks of 256): ctxp[bh][p][d][e] = sum k[d,n]v[e,n]
// Full 3-term (kh/kl x vh/vl) — precision anchor for the d x e contraction.
// ===========================================================================
#define PK_B 272
#define CT_B (64 * PK_B)
#define CTX_SMEM_BYTES (4 * CT_B)

__global__ void __launch_bounds__(128, 2)
context_part()
{
    extern __shared__ char smem[];
    const uint32_t sb = smem_u32(smem);
    int bh = blockIdx.x;
    int p  = blockIdx.y;
    int b = bh >> 2, h = bh & 3;
    const __half* Kh = g_kh + ((size_t)b * HID + h * Dd) * Nn;
    const __half* Kl = g_kl + ((size_t)b * HID + h * Dd) * Nn;
    const __half* Vh = g_vh + ((size_t)b * HID + h * Dd) * Nn;
    const __half* Vl = g_vl + ((size_t)b * HID + h * Dd) * Nn;

    const int tid  = threadIdx.x;
    const int wid  = tid >> 5;
    const int lane = tid & 31;
    const int wm = (wid >> 1) * 32;
    const int wn = (wid & 1) * 32;

    float acc[2][4][4];
    #pragma unroll
    for (int i = 0; i < 2; i++)
        #pragma unroll
        for (int j = 0; j < 4; j++)
            #pragma unroll
            for (int r = 0; r < 4; r++) acc[i][j][r] = 0.f;

    const int lr = lane & 15;
    const int lc = (lane >> 4) & 1;
    const uint32_t kHb = sb;
    const uint32_t kLb = kHb + CT_B;
    const uint32_t vHb = kLb + CT_B;
    const uint32_t vLb = vHb + CT_B;

    #pragma unroll 1
    for (int sl = 0; sl < 2; sl++) {
        const int nn = p * 256 + sl * 128;
        __syncthreads();
        #pragma unroll
        for (int q = 0; q < 8; q++) {
            int id = tid + q * 128;
            int row = id >> 4, ch = id & 15;
            size_t go = (size_t)row * Nn + nn + ch * 8;
            uint32_t off = row * PK_B + ch * 16;
            CP_ASYNC16(kHb + off, Kh + go);
            CP_ASYNC16(kLb + off, Kl + go);
            CP_ASYNC16(vHb + off, Vh + go);
            CP_ASYNC16(vLb + off, Vl + go);
        }
        CP_COMMIT();
        CP_WAIT(0);
        __syncthreads();

        #pragma unroll
        for (int ks = 0; ks < 8; ks++) {
            uint32_t bhf[2][4], blf[2][4];
            #pragma unroll
            for (int fnp = 0; fnp < 2; fnp++) {
                uint32_t off = (uint32_t)(wn + fnp * 16 + lc * 8 + (lane & 7)) * PK_B
                             + (uint32_t)(ks * 32 + ((lane >> 3) & 1) * 16);
                LDM_X4(bhf[fnp], vHb + off);
                LDM_X4(blf[fnp], vLb + off);
            }
            #pragma unroll
            for (int fm = 0; fm < 2; fm++) {
                uint32_t off = (uint32_t)(wm + fm * 16 + lr) * PK_B
                             + (uint32_t)(ks * 32 + lc * 16);
                uint32_t ah[4], al[4];
                LDM_X4(ah, kHb + off);
                LDM_X4(al, kLb + off);
                #pragma unroll
                for (int fn = 0; fn < 4; fn++)
                    mma16(acc[fm][fn], ah, &bhf[fn >> 1][(fn & 1) * 2]);
                #pragma unroll
                for (int fn = 0; fn < 4; fn++)
                    mma16(acc[fm][fn], ah, &blf[fn >> 1][(fn & 1) * 2]);
                #pragma unroll
                for (int fn = 0; fn < 4; fn++)
                    mma16(acc[fm][fn], al, &bhf[fn >> 1][(fn & 1) * 2]);
            }
        }
    }

    float* dst = g_ctxp + ((size_t)bh * 16 + p) * (Dd * Dd);
    #pragma unroll
    for (int fm = 0; fm < 2; fm++) {
        int d0 = wm + fm * 16 + (lane >> 2);
        #pragma unroll
        for (int fn = 0; fn < 4; fn++) {
            int e0 = wn + fn * 8 + (lane & 3) * 2;
            dst[d0 * Dd + e0]           = acc[fm][fn][0];
            dst[d0 * Dd + e0 + 1]       = acc[fm][fn][1];
            dst[(d0 + 8) * Dd + e0]     = acc[fm][fn][2];
            dst[(d0 + 8) * Dd + e0 + 1] = acc[fm][fn][3];
        }
    }
}

// ===========================================================================
// W2[b][c][h*64+d] = sum_e w_out[c][h*64+e] * ctx[bh][d][e]; half pairs out.
// ===========================================================================
__global__ void w2_kernel(const float* __restrict__ w_out)
{
    int bh = blockIdx.x;
    int b = bh >> 2, h = bh & 3;
    __shared__ float ctx[Dd * Dd];
    const int tid = threadIdx.x;

    for (int i = tid; i < Dd * Dd; i += 256) {
        float s = 0.f;
        #pragma unroll
        for (int p = 0; p < 16; p++)
            s += g_ctxp[((size_t)bh * 16 + p) * (Dd * Dd) + i];
        ctx[i] = s;
    }
    __syncthreads();

    int c = tid;
    float w[Dd];
    #pragma unroll
    for (int e = 0; e < Dd; e++) w[e] = w_out[c * HID + h * Dd + e];
    #pragma unroll 4
    for (int d = 0; d < Dd; d++) {
        float s = 0.f;
        #pragma unroll
        for (int e = 0; e < Dd; e++) s = fmaf(w[e], ctx[d * Dd + e], s);
        __half hh, ll;
        split_h(s, hh, ll);
        size_t o = ((size_t)b * HID + c) * HID + h * Dd + d;
        g_w2h[o] = hh;
        g_w2l[o] = ll;
    }
}

// ===========================================================================
extern "C" void kernel_launch(void* const* d_in, const int* in_sizes, int n_in,
                              void* d_out, int out_size)
{
    const float* x     = (const float*)d_in[0];
    const float* w_qkv = (const float*)d_in[1];
    const float* w_out = (const float*)d_in[2];
    const float* b_out = (const float*)d_in[3];
    float* out = (float*)d_out;

    __half *xh, *wh, *wl, *qh, *w2h, *w2l;
    cudaGetSymbolAddress((void**)&xh, g_xh);
    cudaGetSymbolAddress((void**)&wh, g_wh);
    cudaGetSymbolAddress((void**)&wl, g_wl);
    cudaGetSymbolAddress((void**)&qh, g_qh);
    cudaGetSymbolAddress((void**)&w2h, g_w2h);
    cudaGetSymbolAddress((void**)&w2l, g_w2l);

    static int init_done = 0;
    if (!init_done) {
        cudaFuncSetAttribute(fused_gemm, cudaFuncAttributeMaxDynamicSharedMemorySize, FG_SMEM);
        cudaFuncSetAttribute(context_part, cudaFuncAttributeMaxDynamicSharedMemorySize, CTX_SMEM_BYTES);
        init_done = 1;
    }

    // 0) x -> fp16 (B operand), w_qkv -> hi/lo pair (A operand)
    {
        int n4 = (Bn * Cc * Nn) / 4;
        half_kernel<<<(n4 + 255) / 256, 256>>>(x, xh, n4);
        int w4 = (O3 * Cc) / 4;
        split_kernel<<<(w4 + 255) / 256, 256>>>(w_qkv, wh, wl, w4);
    }
    // 1) GEMM1: single launch, y selects q/k/v epilogue
    {
        dim3 grid(Nn / 128, O3 / 128, Bn);
        fused_gemm<<<grid, 256, FG_SMEM>>>(wh, wl, 0,
                                           xh, (size_t)Cc * Nn,
                                           0, nullptr, nullptr);
    }
    // 2) softmax over n on k
    softmax_k_kernel<<<Bn * HID, 256>>>();
    // 3) context partials (3-term)
    {
        dim3 gridc(Bn * Hh, 16);
        context_part<<<gridc, 128, CTX_SMEM_BYTES>>>();
    }
    // 4) W2
    w2_kernel<<<Bn * Hh, 256>>>(w_out);
    // 5) GEMM2: out = W2 @ q + bias (A = w2 pair, B = q fp16)
    {
        dim3 grid2(Nn / 128, HID / 128, Bn);
        fused_gemm<<<grid2, 256, FG_SMEM>>>(w2h, w2l, (size_t)HID * HID,
                                            qh, (size_t)HID * Nn,
                                            1, b_out, out);
    }
}

// round 12
// speedup vs baseline: 1.3963x; 1.1383x over previous
#include <cuda_runtime.h>
#include <cuda_fp16.h>
#include <math.h>
#include <stdint.h>

// Problem constants
#define Bn   16
#define Cc   256
#define Nn   4096
#define Hh   4
#define Dd   64
#define O3   768
#define HID  256
#define SCALE 0.125f

// Scratch
__device__ __half g_xh[(size_t)Bn * Cc * Nn];     // x fp16 (B operand)
__device__ __half g_wh[O3 * Cc];                  // w_qkv hi
__device__ __half g_wl[O3 * Cc];                  // w_qkv lo
__device__ __half g_qh[(size_t)Bn * HID * Nn];    // q softmaxed fp16
__device__ __half g_kh[(size_t)Bn * HID * Nn];    // k fp16 (pre+post softmax, in place)
__device__ __half g_vh[(size_t)Bn * HID * Nn];    // v fp16
__device__ float  g_ctxp[(size_t)Bn * Hh * 16 * Dd * Dd];
__device__ __half g_w2h[(size_t)Bn * HID * HID];
__device__ __half g_w2l[(size_t)Bn * HID * HID];

// ===========================================================================
// Helpers
// ===========================================================================
__device__ __forceinline__ uint32_t smem_u32(const void* p) {
    uint32_t a;
    asm("{ .reg .u64 t; cvta.to.shared.u64 t, %1; cvt.u32.u64 %0, t; }" : "=r"(a) : "l"(p));
    return a;
}
__device__ __forceinline__ void split_h(float x, __half& h, __half& l) {
    h = __float2half_rn(x);
    l = __float2half_rn(x - __half2float(h));
}
__device__ __forceinline__ void mma16(float* d, const uint32_t* a, const uint32_t* b) {
    asm volatile(
        "mma.sync.aligned.m16n8k16.row.col.f32.f16.f16.f32 "
        "{%0,%1,%2,%3},{%4,%5,%6,%7},{%8,%9},{%0,%1,%2,%3};"
        : "+f"(d[0]), "+f"(d[1]), "+f"(d[2]), "+f"(d[3])
        : "r"(a[0]), "r"(a[1]), "r"(a[2]), "r"(a[3]), "r"(b[0]), "r"(b[1]));
}
#define LDM_X4(r, addr) \
    asm volatile("ldmatrix.sync.aligned.m8n8.x4.shared.b16 {%0,%1,%2,%3}, [%4];" \
        : "=r"((r)[0]), "=r"((r)[1]), "=r"((r)[2]), "=r"((r)[3]) : "r"(addr))
#define LDM_X4_T(r, addr) \
    asm volatile("ldmatrix.sync.aligned.m8n8.x4.trans.shared.b16 {%0,%1,%2,%3}, [%4];" \
        : "=r"((r)[0]), "=r"((r)[1]), "=r"((r)[2]), "=r"((r)[3]) : "r"(addr))
#define CP_ASYNC16(dst, src) \
    asm volatile("cp.async.cg.shared.global [%0], [%1], 16;" :: "r"(dst), "l"(src))
#define CP_COMMIT() asm volatile("cp.async.commit_group;" ::: "memory")
#define CP_WAIT(n)  asm volatile("cp.async.wait_group %0;" :: "n"(n) : "memory")

// ===========================================================================
// Conversion kernels
// ===========================================================================
__global__ void half_kernel(const float* __restrict__ src, __half* __restrict__ h, int n4)
{
    int i = blockIdx.x * blockDim.x + threadIdx.x;
    if (i >= n4) return;
    float4 v = *(const float4*)(src + (size_t)i * 4);
    *(half2*)(h + (size_t)i * 4)     = __halves2half2(__float2half_rn(v.x), __float2half_rn(v.y));
    *(half2*)(h + (size_t)i * 4 + 2) = __halves2half2(__float2half_rn(v.z), __float2half_rn(v.w));
}

__global__ void split_kernel(const float* __restrict__ src,
                             __half* __restrict__ h, __half* __restrict__ l, int n4)
{
    int i = blockIdx.x * blockDim.x + threadIdx.x;
    if (i >= n4) return;
    float4 v = *(const float4*)(src + (size_t)i * 4);
    __half h0, l0, h1, l1;
    split_h(v.x, h0, l0); split_h(v.y, h1, l1);
    *(half2*)(h + (size_t)i * 4)     = __halves2half2(h0, h1);
    *(half2*)(l + (size_t)i * 4)     = __halves2half2(l0, l1);
    split_h(v.z, h0, l0); split_h(v.w, h1, l1);
    *(half2*)(h + (size_t)i * 4 + 2) = __halves2half2(h0, h1);
    *(half2*)(l + (size_t)i * 4 + 2) = __halves2half2(l0, l1);
}

// ===========================================================================
// fused_gemm: 2-term fp16-split GEMM (A = hi+lo pair, B = fp16).
// C = A x B, K=256, BK=64 (4 slices), 2-stage cp.async, 2 CTAs/SM.
// Tile 128x128, 8 warps = 2m x 4n (warp 64x32).
// mode 0 (GEMM1): y 0-1 q (fused softmax_d -> fp16), y 2-3 k (fp16),
//                 y 4-5 v (fp16).
// mode 1 (GEMM2): fp32 out + bias.
// ===========================================================================
#define PA_B 144                     // A pitch bytes (64 halves + 16 pad)
#define PB_B 272                     // B pitch bytes (128 halves + 16 pad)
#define A_ST (128 * PA_B)            // 18432
#define B_ST (64 * PB_B)             // 17408
#define STG  (2 * A_ST + B_ST)       // 54272 (Ah, Al, Bh)
#define FG_SMEM (2 * STG)            // 108544 -> 2 CTAs/SM

__global__ void __launch_bounds__(256, 2)
fused_gemm(const __half* __restrict__ Ah, const __half* __restrict__ Al, size_t aStride,
           const __half* __restrict__ Bh, size_t bStride,
           int mode, const float* __restrict__ bias, float* __restrict__ outF)
{
    extern __shared__ char smem[];
    const uint32_t sb = smem_u32(smem);
    const int tid  = threadIdx.x;
    const int wid  = tid >> 5;
    const int lane = tid & 31;
    const int wm   = (wid >> 2) * 64;
    const int wn   = (wid & 3) * 32;
    const int mBlk = blockIdx.y * 128;
    const int nBlk = blockIdx.x * 128;
    const int z    = blockIdx.z;

    const __half* Agh = Ah + (size_t)z * aStride + (size_t)mBlk * 256;
    const __half* Agl = Al + (size_t)z * aStride + (size_t)mBlk * 256;
    const __half* Bg  = Bh + (size_t)z * bStride + nBlk;

    float acc[4][4][4];
    #pragma unroll
    for (int i = 0; i < 4; i++)
        #pragma unroll
        for (int j = 0; j < 4; j++)
            #pragma unroll
            for (int r = 0; r < 4; r++) acc[i][j][r] = 0.f;

    auto issue = [&](int s, int buf) {
        const int kk = s * 64;
        const uint32_t st = sb + buf * STG;
        #pragma unroll
        for (int p = 0; p < 4; p++) {            // A: 128 rows x 8 chunks, hi+lo
            int id = tid + p * 256;
            int m = id >> 3, ch = id & 7;
            size_t go = (size_t)m * 256 + kk + ch * 8;
            uint32_t dst = st + m * PA_B + ch * 16;
            CP_ASYNC16(dst, Agh + go);
            CP_ASYNC16(dst + A_ST, Agl + go);
        }
        #pragma unroll
        for (int p = 0; p < 4; p++) {            // B: 64 rows x 16 chunks
            int id = tid + p * 256;
            int r = id >> 4, ch = id & 15;
            size_t go = (size_t)(kk + r) * Nn + ch * 8;
            CP_ASYNC16(st + 2 * A_ST + r * PB_B + ch * 16, Bg + go);
        }
    };

    const int lr = lane & 15;
    const int lc = (lane >> 4) & 1;

    auto compute = [&](int buf) {
        const uint32_t aHb = sb + buf * STG;
        const uint32_t aLb = aHb + A_ST;
        const uint32_t bHb = aLb + A_ST;
        #pragma unroll
        for (int ks = 0; ks < 4; ks++) {
            uint32_t bh[2][4];
            #pragma unroll
            for (int fnp = 0; fnp < 2; fnp++) {
                uint32_t off = (uint32_t)(ks * 16 + lr) * PB_B
                             + (uint32_t)(wn + fnp * 16 + lc * 8) * 2;
                LDM_X4_T(bh[fnp], bHb + off);
            }
            #pragma unroll
            for (int fm = 0; fm < 4; fm++) {
                uint32_t off = (uint32_t)(wm + fm * 16 + lr) * PA_B
                             + (uint32_t)(ks * 16 + lc * 8) * 2;
                uint32_t ah[4], al[4];
                LDM_X4(ah, aHb + off);
                LDM_X4(al, aLb + off);
                #pragma unroll
                for (int fn = 0; fn < 4; fn++)
                    mma16(acc[fm][fn], ah, &bh[fn >> 1][(fn & 1) * 2]);
                #pragma unroll
                for (int fn = 0; fn < 4; fn++)
                    mma16(acc[fm][fn], al, &bh[fn >> 1][(fn & 1) * 2]);
            }
        }
    };

    issue(0, 0); CP_COMMIT();
    issue(1, 1); CP_COMMIT();
    #pragma unroll 1
    for (int s = 0; s < 4; s++) {
        if (s < 3) { CP_WAIT(1); } else { CP_WAIT(0); }
        __syncthreads();
        compute(s & 1);
        if (s + 2 < 4) {
            __syncthreads();
            issue(s + 2, s & 1); CP_COMMIT();
        }
    }

    // ------------------------------ epilogues ------------------------------
    if (mode == 1) {
        float* Cg = outF + (size_t)z * HID * Nn;
        #pragma unroll
        for (int fm = 0; fm < 4; fm++) {
            int row = mBlk + wm + fm * 16 + (lane >> 2);
            float b0 = bias[row], b8 = bias[row + 8];
            #pragma unroll
            for (int fn = 0; fn < 4; fn++) {
                int col = nBlk + wn + fn * 8 + (lane & 3) * 2;
                float2 v0 = { acc[fm][fn][0] + b0, acc[fm][fn][1] + b0 };
                float2 v1 = { acc[fm][fn][2] + b8, acc[fm][fn][3] + b8 };
                *(float2*)&Cg[(size_t)row * Nn + col]       = v0;
                *(float2*)&Cg[(size_t)(row + 8) * Nn + col] = v1;
            }
        }
        return;
    }

    const int y = blockIdx.y;
    if (y >= 2) {    // K or V: plain fp16
        __half* Oh = (y < 4 ? g_kh : g_vh)
                   + ((size_t)z * HID + mBlk - (y < 4 ? 256 : 512)) * Nn;
        #pragma unroll
        for (int fm = 0; fm < 4; fm++) {
            int row = wm + fm * 16 + (lane >> 2);
            #pragma unroll
            for (int fn = 0; fn < 4; fn++) {
                int col = nBlk + wn + fn * 8 + (lane & 3) * 2;
                *(half2*)&Oh[(size_t)row * Nn + col] =
                    __halves2half2(__float2half_rn(acc[fm][fn][0]),
                                   __float2half_rn(acc[fm][fn][1]));
                *(half2*)&Oh[(size_t)(row + 8) * Nn + col] =
                    __halves2half2(__float2half_rn(acc[fm][fn][2]),
                                   __float2half_rn(acc[fm][fn][3]));
            }
        }
        return;
    }

    // Q: fused softmax over d (2 heads per 128-row tile), x SCALE, fp16 out
    {
        float* S    = (float*)smem;                       // [128][132]
        float* cInv = (float*)(smem + 128 * 132 * 4);     // [256]
        __syncthreads();
        #pragma unroll
        for (int fm = 0; fm < 4; fm++) {
            int row = wm + fm * 16 + (lane >> 2);
            #pragma unroll
            for (int fn = 0; fn < 4; fn++) {
                int col = wn + fn * 8 + (lane & 3) * 2;
                *(float2*)&S[row * 132 + col]       = make_float2(acc[fm][fn][0], acc[fm][fn][1]);
                *(float2*)&S[(row + 8) * 132 + col] = make_float2(acc[fm][fn][2], acc[fm][fn][3]);
            }
        }
        __syncthreads();

        {
            int colI = tid & 127;
            int hf   = tid >> 7;
            float mx = -INFINITY;
            #pragma unroll 4
            for (int r = 0; r < 64; r++)
                mx = fmaxf(mx, S[(hf * 64 + r) * 132 + colI]);
            float sum = 0.f;
            #pragma unroll 4
            for (int r = 0; r < 64; r++) {
                float e = __expf(S[(hf * 64 + r) * 132 + colI] - mx);
                S[(hf * 64 + r) * 132 + colI] = e;
                sum += e;
            }
            cInv[tid] = SCALE / sum;
        }
        __syncthreads();

        __half* Qh = g_qh + ((size_t)z * HID + mBlk) * Nn + nBlk;
        int c2   = (tid & 63) * 2;
        int rgrp = tid >> 6;
        #pragma unroll 4
        for (int rr = 0; rr < 32; rr++) {
            int row = rgrp * 32 + rr;
            int ci  = ((row >> 6) << 7) | c2;
            float2 v = *(float2*)&S[row * 132 + c2];
            *(half2*)&Qh[(size_t)row * Nn + c2] =
                __halves2half2(__float2half_rn(v.x * cInv[ci]),
                               __float2half_rn(v.y * cInv[ci + 1]));
        }
    }
}

// ===========================================================================
// Softmax over n on k: fp16 in/out, in place. One block per (b,hd) row.
// ===========================================================================
__global__ void softmax_k_kernel()
{
    int row = blockIdx.x;
    size_t base = (size_t)row * Nn;
    __shared__ float red[256];
    const int tid = threadIdx.x;
    float v[16];
    float mx = -INFINITY;
    #pragma unroll
    for (int i = 0; i < 16; i++) {
        v[i] = __half2float(g_kh[base + tid + i * 256]);
        mx = fmaxf(mx, v[i]);
    }
    red[tid] = mx; __syncthreads();
    for (int s = 128; s > 0; s >>= 1) { if (tid < s) red[tid] = fmaxf(red[tid], red[tid + s]); __syncthreads(); }
    mx = red[0]; __syncthreads();
    float sum = 0.f;
    #pragma unroll
    for (int i = 0; i < 16; i++) { v[i] = __expf(v[i] - mx); sum += v[i]; }
    red[tid] = sum; __syncthreads();
    for (int s = 128; s > 0; s >>= 1) { if (tid < s) red[tid] += red[tid + s]; __syncthreads(); }
    float inv = 1.f / red[0];
    #pragma unroll
    for (int i = 0; i < 16; i++)
        g_kh[base + tid + i * 256] = __float2half_rn(v[i] * inv);
}

// ===========================================================================
// Context partials (16 n-chunks of 256): ctxp[bh][p][d][e] = sum k[d,n]v[e,n]
// Single-term fp16 x fp16.
// ===========================================================================
#define PK_B 272
#define CT_B (64 * PK_B)
#define CTX_SMEM_BYTES (2 * CT_B)     // 34816: kH, vH

__global__ void __launch_bounds__(128, 4)
context_part()
{
    extern __shared__ char smem[];
    const uint32_t sb = smem_u32(smem);
    int bh = blockIdx.x;
    int p  = blockIdx.y;
    int b = bh >> 2, h = bh & 3;
    const __half* Kh = g_kh + ((size_t)b * HID + h * Dd) * Nn;
    const __half* Vh = g_vh + ((size_t)b * HID + h * Dd) * Nn;

    const int tid  = threadIdx.x;
    const int wid  = tid >> 5;
    const int lane = tid & 31;
    const int wm = (wid >> 1) * 32;
    const int wn = (wid & 1) * 32;

    float acc[2][4][4];
    #pragma unroll
    for (int i = 0; i < 2; i++)
        #pragma unroll
        for (int j = 0; j < 4; j++)
            #pragma unroll
            for (int r = 0; r < 4; r++) acc[i][j][r] = 0.f;

    const int lr = lane & 15;
    const int lc = (lane >> 4) & 1;
    const uint32_t kHb = sb;
    const uint32_t vHb = kHb + CT_B;

    #pragma unroll 1
    for (int sl = 0; sl < 2; sl++) {
        const int nn = p * 256 + sl * 128;
        __syncthreads();
        #pragma unroll
        for (int q = 0; q < 8; q++) {
            int id = tid + q * 128;
            int row = id >> 4, ch = id & 15;
            size_t go = (size_t)row * Nn + nn + ch * 8;
            uint32_t off = row * PK_B + ch * 16;
            CP_ASYNC16(kHb + off, Kh + go);
            CP_ASYNC16(vHb + off, Vh + go);
        }
        CP_COMMIT();
        CP_WAIT(0);
        __syncthreads();

        #pragma unroll
        for (int ks = 0; ks < 8; ks++) {
            uint32_t bhf[2][4];
            #pragma unroll
            for (int fnp = 0; fnp < 2; fnp++) {
                uint32_t off = (uint32_t)(wn + fnp * 16 + lc * 8 + (lane & 7)) * PK_B
                             + (uint32_t)(ks * 32 + ((lane >> 3) & 1) * 16);
                LDM_X4(bhf[fnp], vHb + off);
            }
            #pragma unroll
            for (int fm = 0; fm < 2; fm++) {
                uint32_t off = (uint32_t)(wm + fm * 16 + lr) * PK_B
                             + (uint32_t)(ks * 32 + lc * 16);
                uint32_t ah[4];
                LDM_X4(ah, kHb + off);
                #pragma unroll
                for (int fn = 0; fn < 4; fn++)
                    mma16(acc[fm][fn], ah, &bhf[fn >> 1][(fn & 1) * 2]);
            }
        }
    }

    float* dst = g_ctxp + ((size_t)bh * 16 + p) * (Dd * Dd);
    #pragma unroll
    for (int fm = 0; fm < 2; fm++) {
        int d0 = wm + fm * 16 + (lane >> 2);
        #pragma unroll
        for (int fn = 0; fn < 4; fn++) {
            int e0 = wn + fn * 8 + (lane & 3) * 2;
            dst[d0 * Dd + e0]           = acc[fm][fn][0];
            dst[d0 * Dd + e0 + 1]       = acc[fm][fn][1];
            dst[(d0 + 8) * Dd + e0]     = acc[fm][fn][2];
            dst[(d0 + 8) * Dd + e0 + 1] = acc[fm][fn][3];
        }
    }
}

// ===========================================================================
// W2[b][c][h*64+d] = sum_e w_out[c][h*64+e] * ctx[bh][d][e]; half pairs out.
// ===========================================================================
__global__ void w2_kernel(const float* __restrict__ w_out)
{
    int bh = blockIdx.x;
    int b = bh >> 2, h = bh & 3;
    __shared__ float ctx[Dd * Dd];
    const int tid = threadIdx.x;

    for (int i = tid; i < Dd * Dd; i += 256) {
        float s = 0.f;
        #pragma unroll
        for (int p = 0; p < 16; p++)
            s += g_ctxp[((size_t)bh * 16 + p) * (Dd * Dd) + i];
        ctx[i] = s;
    }
    __syncthreads();

    int c = tid;
    float w[Dd];
    #pragma unroll
    for (int e = 0; e < Dd; e++) w[e] = w_out[c * HID + h * Dd + e];
    #pragma unroll 4
    for (int d = 0; d < Dd; d++) {
        float s = 0.f;
        #pragma unroll
        for (int e = 0; e < Dd; e++) s = fmaf(w[e], ctx[d * Dd + e], s);
        __half hh, ll;
        split_h(s, hh, ll);
        size_t o = ((size_t)b * HID + c) * HID + h * Dd + d;
        g_w2h[o] = hh;
        g_w2l[o] = ll;
    }
}

// ===========================================================================
extern "C" void kernel_launch(void* const* d_in, const int* in_sizes, int n_in,
                              void* d_out, int out_size)
{
    const float* x     = (const float*)d_in[0];
    const float* w_qkv = (const float*)d_in[1];
    const float* w_out = (const float*)d_in[2];
    const float* b_out = (const float*)d_in[3];
    float* out = (float*)d_out;

    __half *xh, *wh, *wl, *qh, *w2h, *w2l;
    cudaGetSymbolAddress((void**)&xh, g_xh);
    cudaGetSymbolAddress((void**)&wh, g_wh);
    cudaGetSymbolAddress((void**)&wl, g_wl);
    cudaGetSymbolAddress((void**)&qh, g_qh);
    cudaGetSymbolAddress((void**)&w2h, g_w2h);
    cudaGetSymbolAddress((void**)&w2l, g_w2l);

    static int init_done = 0;
    if (!init_done) {
        cudaFuncSetAttribute(fused_gemm, cudaFuncAttributeMaxDynamicSharedMemorySize, FG_SMEM);
        cudaFuncSetAttribute(context_part, cudaFuncAttributeMaxDynamicSharedMemorySize, CTX_SMEM_BYTES);
        init_done = 1;
    }

    // 0) x -> fp16, w_qkv -> hi/lo pair
    {
        int n4 = (Bn * Cc * Nn) / 4;
        half_kernel<<<(n4 + 255) / 256, 256>>>(x, xh, n4);
        int w4 = (O3 * Cc) / 4;
        split_kernel<<<(w4 + 255) / 256, 256>>>(w_qkv, wh, wl, w4);
    }
    // 1) GEMM1: single launch, y selects q/k/v epilogue
    {
        dim3 grid(Nn / 128, O3 / 128, Bn);
        fused_gemm<<<grid, 256, FG_SMEM>>>(wh, wl, 0,
                                           xh, (size_t)Cc * Nn,
                                           0, nullptr, nullptr);
    }
    // 2) softmax over n on k (in place, fp16)
    softmax_k_kernel<<<Bn * HID, 256>>>();
    // 3) context partials (single-term fp16)
    {
        dim3 gridc(Bn * Hh, 16);
        context_part<<<gridc, 128, CTX_SMEM_BYTES>>>();
    }
    // 4) W2
    w2_kernel<<<Bn * Hh, 256>>>(w_out);
    // 5) GEMM2: out = W2 @ q + bias (A = w2 pair, B = q fp16)
    {
        dim3 grid2(Nn / 128, HID / 128, Bn);
        fused_gemm<<<grid2, 256, FG_SMEM>>>(w2h, w2l, (size_t)HID * HID,
                                            qh, (size_t)HID * Nn,
                                            1, b_out, out);
    }
}

// round 13
// speedup vs baseline: 1.9294x; 1.3818x over previous
#include <cuda_runtime.h>
#include <cuda_fp16.h>
#include <math.h>
#include <stdint.h>

// Problem constants
#define Bn   16
#define Cc   256
#define Nn   4096
#define Hh   4
#define Dd   64
#define O3   768
#define HID  256
#define SCALE 0.125f

// Scratch (pure fp16 operand pipeline, fp32 accumulation everywhere)
__device__ __half g_xh[(size_t)Bn * Cc * Nn];     // x fp16
__device__ __half g_wh[O3 * Cc];                  // w_qkv fp16
__device__ __half g_qh[(size_t)Bn * HID * Nn];    // q softmaxed fp16
__device__ __half g_kh[(size_t)Bn * HID * Nn];    // k fp16 (softmaxed in place)
__device__ __half g_vh[(size_t)Bn * HID * Nn];    // v fp16
__device__ float  g_ctxp[(size_t)Bn * Hh * 16 * Dd * Dd];
__device__ __half g_w2h[(size_t)Bn * HID * HID];  // w_out @ ctx^T fp16

// ===========================================================================
// Helpers
// ===========================================================================
__device__ __forceinline__ uint32_t smem_u32(const void* p) {
    uint32_t a;
    asm("{ .reg .u64 t; cvta.to.shared.u64 t, %1; cvt.u32.u64 %0, t; }" : "=r"(a) : "l"(p));
    return a;
}
__device__ __forceinline__ void mma16(float* d, const uint32_t* a, const uint32_t* b) {
    asm volatile(
        "mma.sync.aligned.m16n8k16.row.col.f32.f16.f16.f32 "
        "{%0,%1,%2,%3},{%4,%5,%6,%7},{%8,%9},{%0,%1,%2,%3};"
        : "+f"(d[0]), "+f"(d[1]), "+f"(d[2]), "+f"(d[3])
        : "r"(a[0]), "r"(a[1]), "r"(a[2]), "r"(a[3]), "r"(b[0]), "r"(b[1]));
}
#define LDM_X4(r, addr) \
    asm volatile("ldmatrix.sync.aligned.m8n8.x4.shared.b16 {%0,%1,%2,%3}, [%4];" \
        : "=r"((r)[0]), "=r"((r)[1]), "=r"((r)[2]), "=r"((r)[3]) : "r"(addr))
#define LDM_X4_T(r, addr) \
    asm volatile("ldmatrix.sync.aligned.m8n8.x4.trans.shared.b16 {%0,%1,%2,%3}, [%4];" \
        : "=r"((r)[0]), "=r"((r)[1]), "=r"((r)[2]), "=r"((r)[3]) : "r"(addr))
#define CP_ASYNC16(dst, src) \
    asm volatile("cp.async.cg.shared.global [%0], [%1], 16;" :: "r"(dst), "l"(src))
#define CP_COMMIT() asm volatile("cp.async.commit_group;" ::: "memory")
#define CP_WAIT(n)  asm volatile("cp.async.wait_group %0;" :: "n"(n) : "memory")

// ===========================================================================
// fp32 -> fp16 conversion
// ===========================================================================
__global__ void half_kernel(const float* __restrict__ src, __half* __restrict__ h, int n4)
{
    int i = blockIdx.x * blockDim.x + threadIdx.x;
    if (i >= n4) return;
    float4 v = *(const float4*)(src + (size_t)i * 4);
    *(half2*)(h + (size_t)i * 4)     = __halves2half2(__float2half_rn(v.x), __float2half_rn(v.y));
    *(half2*)(h + (size_t)i * 4 + 2) = __halves2half2(__float2half_rn(v.z), __float2half_rn(v.w));
}

// ===========================================================================
// fused_gemm: plain fp16 GEMM, fp32 accumulate.
// C = A x B, K=256, BK=64 (4 slices), 2-stage cp.async, 2 CTAs/SM.
// Tile 128x128, 8 warps = 2m x 4n (warp 64x32).
// mode 0 (GEMM1): y 0-1 q (fused softmax_d -> fp16), y 2-3 k, y 4-5 v.
// mode 1 (GEMM2): fp32 out + bias.
// ===========================================================================
#define PA_B 144                     // A pitch bytes (64 halves + 16 pad)
#define PB_B 272                     // B pitch bytes (128 halves + 16 pad)
#define A_ST (128 * PA_B)            // 18432
#define B_ST (64 * PB_B)             // 17408
#define STG  (A_ST + B_ST)           // 35840
#define FG_SMEM (2 * STG)            // 71680 -> 2 CTAs/SM

__global__ void __launch_bounds__(256, 2)
fused_gemm(const __half* __restrict__ Ah, size_t aStride,
           const __half* __restrict__ Bh, size_t bStride,
           int mode, const float* __restrict__ bias, float* __restrict__ outF)
{
    extern __shared__ char smem[];
    const uint32_t sb = smem_u32(smem);
    const int tid  = threadIdx.x;
    const int wid  = tid >> 5;
    const int lane = tid & 31;
    const int wm   = (wid >> 2) * 64;
    const int wn   = (wid & 3) * 32;
    const int mBlk = blockIdx.y * 128;
    const int nBlk = blockIdx.x * 128;
    const int z    = blockIdx.z;

    const __half* Ag = Ah + (size_t)z * aStride + (size_t)mBlk * 256;
    const __half* Bg = Bh + (size_t)z * bStride + nBlk;

    float acc[4][4][4];
    #pragma unroll
    for (int i = 0; i < 4; i++)
        #pragma unroll
        for (int j = 0; j < 4; j++)
            #pragma unroll
            for (int r = 0; r < 4; r++) acc[i][j][r] = 0.f;

    auto issue = [&](int s, int buf) {
        const int kk = s * 64;
        const uint32_t st = sb + buf * STG;
        #pragma unroll
        for (int p = 0; p < 4; p++) {            // A: 128 rows x 8 chunks
            int id = tid + p * 256;
            int m = id >> 3, ch = id & 7;
            size_t go = (size_t)m * 256 + kk + ch * 8;
            CP_ASYNC16(st + m * PA_B + ch * 16, Ag + go);
        }
        #pragma unroll
        for (int p = 0; p < 4; p++) {            // B: 64 rows x 16 chunks
            int id = tid + p * 256;
            int r = id >> 4, ch = id & 15;
            size_t go = (size_t)(kk + r) * Nn + ch * 8;
            CP_ASYNC16(st + A_ST + r * PB_B + ch * 16, Bg + go);
        }
    };

    const int lr = lane & 15;
    const int lc = (lane >> 4) & 1;

    auto compute = [&](int buf) {
        const uint32_t aHb = sb + buf * STG;
        const uint32_t bHb = aHb + A_ST;
        #pragma unroll
        for (int ks = 0; ks < 4; ks++) {
            uint32_t bh[2][4];
            #pragma unroll
            for (int fnp = 0; fnp < 2; fnp++) {
                uint32_t off = (uint32_t)(ks * 16 + lr) * PB_B
                             + (uint32_t)(wn + fnp * 16 + lc * 8) * 2;
                LDM_X4_T(bh[fnp], bHb + off);
            }
            #pragma unroll
            for (int fm = 0; fm < 4; fm++) {
                uint32_t off = (uint32_t)(wm + fm * 16 + lr) * PA_B
                             + (uint32_t)(ks * 16 + lc * 8) * 2;
                uint32_t ah[4];
                LDM_X4(ah, aHb + off);
                #pragma unroll
                for (int fn = 0; fn < 4; fn++)
                    mma16(acc[fm][fn], ah, &bh[fn >> 1][(fn & 1) * 2]);
            }
        }
    };

    issue(0, 0); CP_COMMIT();
    issue(1, 1); CP_COMMIT();
    #pragma unroll 1
    for (int s = 0; s < 4; s++) {
        if (s < 3) { CP_WAIT(1); } else { CP_WAIT(0); }
        __syncthreads();
        compute(s & 1);
        if (s + 2 < 4) {
            __syncthreads();
            issue(s + 2, s & 1); CP_COMMIT();
        }
    }

    // ------------------------------ epilogues ------------------------------
    if (mode == 1) {
        float* Cg = outF + (size_t)z * HID * Nn;
        #pragma unroll
        for (int fm = 0; fm < 4; fm++) {
            int row = mBlk + wm + fm * 16 + (lane >> 2);
            float b0 = bias[row], b8 = bias[row + 8];
            #pragma unroll
            for (int fn = 0; fn < 4; fn++) {
                int col = nBlk + wn + fn * 8 + (lane & 3) * 2;
                float2 v0 = { acc[fm][fn][0] + b0, acc[fm][fn][1] + b0 };
                float2 v1 = { acc[fm][fn][2] + b8, acc[fm][fn][3] + b8 };
                *(float2*)&Cg[(size_t)row * Nn + col]       = v0;
                *(float2*)&Cg[(size_t)(row + 8) * Nn + col] = v1;
            }
        }
        return;
    }

    const int y = blockIdx.y;
    if (y >= 2) {    // K or V: plain fp16
        __half* Oh = (y < 4 ? g_kh : g_vh)
                   + ((size_t)z * HID + mBlk - (y < 4 ? 256 : 512)) * Nn;
        #pragma unroll
        for (int fm = 0; fm < 4; fm++) {
            int row = wm + fm * 16 + (lane >> 2);
            #pragma unroll
            for (int fn = 0; fn < 4; fn++) {
                int col = nBlk + wn + fn * 8 + (lane & 3) * 2;
                *(half2*)&Oh[(size_t)row * Nn + col] =
                    __halves2half2(__float2half_rn(acc[fm][fn][0]),
                                   __float2half_rn(acc[fm][fn][1]));
                *(half2*)&Oh[(size_t)(row + 8) * Nn + col] =
                    __halves2half2(__float2half_rn(acc[fm][fn][2]),
                                   __float2half_rn(acc[fm][fn][3]));
            }
        }
        return;
    }

    // Q: fused softmax over d (2 heads per 128-row tile), x SCALE, fp16 out
    {
        float* S    = (float*)smem;                       // [128][132]
        float* cInv = (float*)(smem + 128 * 132 * 4);     // [256]
        __syncthreads();
        #pragma unroll
        for (int fm = 0; fm < 4; fm++) {
            int row = wm + fm * 16 + (lane >> 2);
            #pragma unroll
            for (int fn = 0; fn < 4; fn++) {
                int col = wn + fn * 8 + (lane & 3) * 2;
                *(float2*)&S[row * 132 + col]       = make_float2(acc[fm][fn][0], acc[fm][fn][1]);
                *(float2*)&S[(row + 8) * 132 + col] = make_float2(acc[fm][fn][2], acc[fm][fn][3]);
            }
        }
        __syncthreads();

        {
            int colI = tid & 127;
            int hf   = tid >> 7;
            float mx = -INFINITY;
            #pragma unroll 4
            for (int r = 0; r < 64; r++)
                mx = fmaxf(mx, S[(hf * 64 + r) * 132 + colI]);
            float sum = 0.f;
            #pragma unroll 4
            for (int r = 0; r < 64; r++) {
                float e = __expf(S[(hf * 64 + r) * 132 + colI] - mx);
                S[(hf * 64 + r) * 132 + colI] = e;
                sum += e;
            }
            cInv[tid] = SCALE / sum;
        }
        __syncthreads();

        __half* Qh = g_qh + ((size_t)z * HID + mBlk) * Nn + nBlk;
        int c2   = (tid & 63) * 2;
        int rgrp = tid >> 6;
        #pragma unroll 4
        for (int rr = 0; rr < 32; rr++) {
            int row = rgrp * 32 + rr;
            int ci  = ((row >> 6) << 7) | c2;
            float2 v = *(float2*)&S[row * 132 + c2];
            *(half2*)&Qh[(size_t)row * Nn + c2] =
                __halves2half2(__float2half_rn(v.x * cInv[ci]),
                               __float2half_rn(v.y * cInv[ci + 1]));
        }
    }
}

// ===========================================================================
// Softmax over n on k: fp16 in/out, in place. One block per (b,hd) row.
// ===========================================================================
__global__ void softmax_k_kernel()
{
    int row = blockIdx.x;
    size_t base = (size_t)row * Nn;
    __shared__ float red[256];
    const int tid = threadIdx.x;
    float v[16];
    float mx = -INFINITY;
    #pragma unroll
    for (int i = 0; i < 16; i++) {
        v[i] = __half2float(g_kh[base + tid + i * 256]);
        mx = fmaxf(mx, v[i]);
    }
    red[tid] = mx; __syncthreads();
    for (int s = 128; s > 0; s >>= 1) { if (tid < s) red[tid] = fmaxf(red[tid], red[tid + s]); __syncthreads(); }
    mx = red[0]; __syncthreads();
    float sum = 0.f;
    #pragma unroll
    for (int i = 0; i < 16; i++) { v[i] = __expf(v[i] - mx); sum += v[i]; }
    red[tid] = sum; __syncthreads();
    for (int s = 128; s > 0; s >>= 1) { if (tid < s) red[tid] += red[tid + s]; __syncthreads(); }
    float inv = 1.f / red[0];
    #pragma unroll
    for (int i = 0; i < 16; i++)
        g_kh[base + tid + i * 256] = __float2half_rn(v[i] * inv);
}

// ===========================================================================
// Context partials (16 n-chunks of 256): ctxp[bh][p][d][e] = sum k[d,n]v[e,n]
// fp16 x fp16 -> fp32.
// ===========================================================================
#define PK_B 272
#define CT_B (64 * PK_B)
#define CTX_SMEM_BYTES (2 * CT_B)     // 34816: kH, vH

__global__ void __launch_bounds__(128, 4)
context_part()
{
    extern __shared__ char smem[];
    const uint32_t sb = smem_u32(smem);
    int bh = blockIdx.x;
    int p  = blockIdx.y;
    int b = bh >> 2, h = bh & 3;
    const __half* Kh = g_kh + ((size_t)b * HID + h * Dd) * Nn;
    const __half* Vh = g_vh + ((size_t)b * HID + h * Dd) * Nn;

    const int tid  = threadIdx.x;
    const int wid  = tid >> 5;
    const int lane = tid & 31;
    const int wm = (wid >> 1) * 32;
    const int wn = (wid & 1) * 32;

    float acc[2][4][4];
    #pragma unroll
    for (int i = 0; i < 2; i++)
        #pragma unroll
        for (int j = 0; j < 4; j++)
            #pragma unroll
            for (int r = 0; r < 4; r++) acc[i][j][r] = 0.f;

    const int lr = lane & 15;
    const int lc = (lane >> 4) & 1;
    const uint32_t kHb = sb;
    const uint32_t vHb = kHb + CT_B;

    #pragma unroll 1
    for (int sl = 0; sl < 2; sl++) {
        const int nn = p * 256 + sl * 128;
        __syncthreads();
        #pragma unroll
        for (int q = 0; q < 8; q++) {
            int id = tid + q * 128;
            int row = id >> 4, ch = id & 15;
            size_t go = (size_t)row * Nn + nn + ch * 8;
            uint32_t off = row * PK_B + ch * 16;
            CP_ASYNC16(kHb + off, Kh + go);
            CP_ASYNC16(vHb + off, Vh + go);
        }
        CP_COMMIT();
        CP_WAIT(0);
        __syncthreads();

        #pragma unroll
        for (int ks = 0; ks < 8; ks++) {
            uint32_t bhf[2][4];
            #pragma unroll
            for (int fnp = 0; fnp < 2; fnp++) {
                uint32_t off = (uint32_t)(wn + fnp * 16 + lc * 8 + (lane & 7)) * PK_B
                             + (uint32_t)(ks * 32 + ((lane >> 3) & 1) * 16);
                LDM_X4(bhf[fnp], vHb + off);
            }
            #pragma unroll
            for (int fm = 0; fm < 2; fm++) {
                uint32_t off = (uint32_t)(wm + fm * 16 + lr) * PK_B
                             + (uint32_t)(ks * 32 + lc * 16);
                uint32_t ah[4];
                LDM_X4(ah, kHb + off);
                #pragma unroll
                for (int fn = 0; fn < 4; fn++)
                    mma16(acc[fm][fn], ah, &bhf[fn >> 1][(fn & 1) * 2]);
            }
        }
    }

    float* dst = g_ctxp + ((size_t)bh * 16 + p) * (Dd * Dd);
    #pragma unroll
    for (int fm = 0; fm < 2; fm++) {
        int d0 = wm + fm * 16 + (lane >> 2);
        #pragma unroll
        for (int fn = 0; fn < 4; fn++) {
            int e0 = wn + fn * 8 + (lane & 3) * 2;
            dst[d0 * Dd + e0]           = acc[fm][fn][0];
            dst[d0 * Dd + e0 + 1]       = acc[fm][fn][1];
            dst[(d0 + 8) * Dd + e0]     = acc[fm][fn][2];
            dst[(d0 + 8) * Dd + e0 + 1] = acc[fm][fn][3];
        }
    }
}

// ===========================================================================
// W2[b][c][h*64+d] = sum_e w_out[c][h*64+e] * ctx[bh][d][e]; fp16 out.
// ===========================================================================
__global__ void w2_kernel(const float* __restrict__ w_out)
{
    int bh = blockIdx.x;
    int b = bh >> 2, h = bh & 3;
    __shared__ float ctx[Dd * Dd];
    const int tid = threadIdx.x;

    for (int i = tid; i < Dd * Dd; i += 256) {
        float s = 0.f;
        #pragma unroll
        for (int p = 0; p < 16; p++)
            s += g_ctxp[((size_t)bh * 16 + p) * (Dd * Dd) + i];
        ctx[i] = s;
    }
    __syncthreads();

    int c = tid;
    float w[Dd];
    #pragma unroll
    for (int e = 0; e < Dd; e++) w[e] = w_out[c * HID + h * Dd + e];
    #pragma unroll 4
    for (int d = 0; d < Dd; d++) {
        float s = 0.f;
        #pragma unroll
        for (int e = 0; e < Dd; e++) s = fmaf(w[e], ctx[d * Dd + e], s);
        g_w2h[((size_t)b * HID + c) * HID + h * Dd + d] = __float2half_rn(s);
    }
}

// ===========================================================================
extern "C" void kernel_launch(void* const* d_in, const int* in_sizes, int n_in,
                              void* d_out, int out_size)
{
    const float* x     = (const float*)d_in[0];
    const float* w_qkv = (const float*)d_in[1];
    const float* w_out = (const float*)d_in[2];
    const float* b_out = (const float*)d_in[3];
    float* out = (float*)d_out;

    __half *xh, *wh, *qh, *w2h;
    cudaGetSymbolAddress((void**)&xh, g_xh);
    cudaGetSymbolAddress((void**)&wh, g_wh);
    cudaGetSymbolAddress((void**)&qh, g_qh);
    cudaGetSymbolAddress((void**)&w2h, g_w2h);

    static int init_done = 0;
    if (!init_done) {
        cudaFuncSetAttribute(fused_gemm, cudaFuncAttributeMaxDynamicSharedMemorySize, FG_SMEM);
        cudaFuncSetAttribute(context_part, cudaFuncAttributeMaxDynamicSharedMemorySize, CTX_SMEM_BYTES);
        init_done = 1;
    }

    // 0) x, w_qkv -> fp16
    {
        int n4 = (Bn * Cc * Nn) / 4;
        half_kernel<<<(n4 + 255) / 256, 256>>>(x, xh, n4);
        int w4 = (O3 * Cc) / 4;
        half_kernel<<<(w4 + 255) / 256, 256>>>(w_qkv, wh, w4);
    }
    // 1) GEMM1: single launch, y selects q/k/v epilogue
    {
        dim3 grid(Nn / 128, O3 / 128, Bn);
        fused_gemm<<<grid, 256, FG_SMEM>>>(wh, 0,
                                           xh, (size_t)Cc * Nn,
                                           0, nullptr, nullptr);
    }
    // 2) softmax over n on k (in place, fp16)
    softmax_k_kernel<<<Bn * HID, 256>>>();
    // 3) context partials
    {
        dim3 gridc(Bn * Hh, 16);
        context_part<<<gridc, 128, CTX_SMEM_BYTES>>>();
    }
    // 4) W2
    w2_kernel<<<Bn * Hh, 256>>>(w_out);
    // 5) GEMM2: out = W2 @ q + bias
    {
        dim3 grid2(Nn / 128, HID / 128, Bn);
        fused_gemm<<<grid2, 256, FG_SMEM>>>(w2h, (size_t)HID * HID,
                                            qh, (size_t)HID * Nn,
                                            1, b_out, out);
    }
}

// round 14
// speedup vs baseline: 1.9297x; 1.0001x over previous
#include <cuda_runtime.h>
#include <cuda_fp16.h>
#include <math.h>
#include <stdint.h>

// Problem constants
#define Bn   16
#define Cc   256
#define Nn   4096
#define Hh   4
#define Dd   64
#define O3   768
#define HID  256
#define SCALE 0.125f

// Scratch (pure fp16 operand pipeline, fp32 accumulation everywhere)
__device__ __half g_xh[(size_t)Bn * Cc * Nn];     // x fp16
__device__ __half g_wh[O3 * Cc];                  // w_qkv fp16
__device__ __half g_qh[(size_t)Bn * HID * Nn];    // q softmaxed fp16
__device__ __half g_kh[(size_t)Bn * HID * Nn];    // k fp16 (softmaxed in place)
__device__ __half g_vh[(size_t)Bn * HID * Nn];    // v fp16
__device__ float  g_ctxp[(size_t)Bn * Hh * 16 * Dd * Dd];
__device__ __half g_w2h[(size_t)Bn * HID * HID];  // w_out @ ctx^T fp16

// ===========================================================================
// Helpers
// ===========================================================================
__device__ __forceinline__ uint32_t smem_u32(const void* p) {
    uint32_t a;
    asm("{ .reg .u64 t; cvta.to.shared.u64 t, %1; cvt.u32.u64 %0, t; }" : "=r"(a) : "l"(p));
    return a;
}
__device__ __forceinline__ void mma16(float* d, const uint32_t* a, const uint32_t* b) {
    asm volatile(
        "mma.sync.aligned.m16n8k16.row.col.f32.f16.f16.f32 "
        "{%0,%1,%2,%3},{%4,%5,%6,%7},{%8,%9},{%0,%1,%2,%3};"
        : "+f"(d[0]), "+f"(d[1]), "+f"(d[2]), "+f"(d[3])
        : "r"(a[0]), "r"(a[1]), "r"(a[2]), "r"(a[3]), "r"(b[0]), "r"(b[1]));
}
#define LDM_X4(r, addr) \
    asm volatile("ldmatrix.sync.aligned.m8n8.x4.shared.b16 {%0,%1,%2,%3}, [%4];" \
        : "=r"((r)[0]), "=r"((r)[1]), "=r"((r)[2]), "=r"((r)[3]) : "r"(addr))
#define LDM_X4_T(r, addr) \
    asm volatile("ldmatrix.sync.aligned.m8n8.x4.trans.shared.b16 {%0,%1,%2,%3}, [%4];" \
        : "=r"((r)[0]), "=r"((r)[1]), "=r"((r)[2]), "=r"((r)[3]) : "r"(addr))
#define CP_ASYNC16(dst, src) \
    asm volatile("cp.async.cg.shared.global [%0], [%1], 16;" :: "r"(dst), "l"(src))
#define CP_COMMIT() asm volatile("cp.async.commit_group;" ::: "memory")
#define CP_WAIT(n)  asm volatile("cp.async.wait_group %0;" :: "n"(n) : "memory")

// ===========================================================================
// fp32 -> fp16 conversion
// ===========================================================================
__global__ void half_kernel(const float* __restrict__ src, __half* __restrict__ h, int n4)
{
    int i = blockIdx.x * blockDim.x + threadIdx.x;
    if (i >= n4) return;
    float4 v = *(const float4*)(src + (size_t)i * 4);
    *(half2*)(h + (size_t)i * 4)     = __halves2half2(__float2half_rn(v.x), __float2half_rn(v.y));
    *(half2*)(h + (size_t)i * 4 + 2) = __halves2half2(__float2half_rn(v.z), __float2half_rn(v.w));
}

// ===========================================================================
// fused_gemm: plain fp16 GEMM, fp32 accumulate.
// C = A x B, K=256, BK=64 (4 slices), 2-stage cp.async, 2 CTAs/SM.
// Tile 128x128, 8 warps = 2m x 4n (warp 64x32).
// mode 0 (GEMM1): section y = blockIdx.y + yOff:
//   y 0-1 q (fused softmax_d -> fp16), y 2-3 k (fp16), y 4-5 v (fp16).
// mode 1 (GEMM2): fp32 out + bias.
// ===========================================================================
#define PA_B 144                     // A pitch bytes (64 halves + 16 pad)
#define PB_B 272                     // B pitch bytes (128 halves + 16 pad)
#define A_ST (128 * PA_B)            // 18432
#define B_ST (64 * PB_B)             // 17408
#define STG  (A_ST + B_ST)           // 35840
#define FG_SMEM (2 * STG)            // 71680 -> 2 CTAs/SM

__global__ void __launch_bounds__(256, 2)
fused_gemm(const __half* __restrict__ Ah, size_t aStride,
           const __half* __restrict__ Bh, size_t bStride,
           int mode, int yOff, const float* __restrict__ bias, float* __restrict__ outF)
{
    extern __shared__ char smem[];
    const uint32_t sb = smem_u32(smem);
    const int tid  = threadIdx.x;
    const int wid  = tid >> 5;
    const int lane = tid & 31;
    const int wm   = (wid >> 2) * 64;
    const int wn   = (wid & 3) * 32;
    const int y    = blockIdx.y + yOff;
    const int mBlk = y * 128;
    const int nBlk = blockIdx.x * 128;
    const int z    = blockIdx.z;

    const __half* Ag = Ah + (size_t)z * aStride + (size_t)mBlk * 256;
    const __half* Bg = Bh + (size_t)z * bStride + nBlk;

    float acc[4][4][4];
    #pragma unroll
    for (int i = 0; i < 4; i++)
        #pragma unroll
        for (int j = 0; j < 4; j++)
            #pragma unroll
            for (int r = 0; r < 4; r++) acc[i][j][r] = 0.f;

    auto issue = [&](int s, int buf) {
        const int kk = s * 64;
        const uint32_t st = sb + buf * STG;
        #pragma unroll
        for (int p = 0; p < 4; p++) {            // A: 128 rows x 8 chunks
            int id = tid + p * 256;
            int m = id >> 3, ch = id & 7;
            size_t go = (size_t)m * 256 + kk + ch * 8;
            CP_ASYNC16(st + m * PA_B + ch * 16, Ag + go);
        }
        #pragma unroll
        for (int p = 0; p < 4; p++) {            // B: 64 rows x 16 chunks
            int id = tid + p * 256;
            int r = id >> 4, ch = id & 15;
            size_t go = (size_t)(kk + r) * Nn + ch * 8;
            CP_ASYNC16(st + A_ST + r * PB_B + ch * 16, Bg + go);
        }
    };

    const int lr = lane & 15;
    const int lc = (lane >> 4) & 1;

    auto compute = [&](int buf) {
        const uint32_t aHb = sb + buf * STG;
        const uint32_t bHb = aHb + A_ST;
        #pragma unroll
        for (int ks = 0; ks < 4; ks++) {
            uint32_t bh[2][4];
            #pragma unroll
            for (int fnp = 0; fnp < 2; fnp++) {
                uint32_t off = (uint32_t)(ks * 16 + lr) * PB_B
                             + (uint32_t)(wn + fnp * 16 + lc * 8) * 2;
                LDM_X4_T(bh[fnp], bHb + off);
            }
            #pragma unroll
            for (int fm = 0; fm < 4; fm++) {
                uint32_t off = (uint32_t)(wm + fm * 16 + lr) * PA_B
                             + (uint32_t)(ks * 16 + lc * 8) * 2;
                uint32_t ah[4];
                LDM_X4(ah, aHb + off);
                #pragma unroll
                for (int fn = 0; fn < 4; fn++)
                    mma16(acc[fm][fn], ah, &bh[fn >> 1][(fn & 1) * 2]);
            }
        }
    };

    issue(0, 0); CP_COMMIT();
    issue(1, 1); CP_COMMIT();
    #pragma unroll 1
    for (int s = 0; s < 4; s++) {
        if (s < 3) { CP_WAIT(1); } else { CP_WAIT(0); }
        __syncthreads();
        compute(s & 1);
        if (s + 2 < 4) {
            __syncthreads();
            issue(s + 2, s & 1); CP_COMMIT();
        }
    }

    // ------------------------------ epilogues ------------------------------
    if (mode == 1) {
        float* Cg = outF + (size_t)z * HID * Nn;
        #pragma unroll
        for (int fm = 0; fm < 4; fm++) {
            int row = mBlk + wm + fm * 16 + (lane >> 2);
            float b0 = bias[row], b8 = bias[row + 8];
            #pragma unroll
            for (int fn = 0; fn < 4; fn++) {
                int col = nBlk + wn + fn * 8 + (lane & 3) * 2;
                float2 v0 = { acc[fm][fn][0] + b0, acc[fm][fn][1] + b0 };
                float2 v1 = { acc[fm][fn][2] + b8, acc[fm][fn][3] + b8 };
                *(float2*)&Cg[(size_t)row * Nn + col]       = v0;
                *(float2*)&Cg[(size_t)(row + 8) * Nn + col] = v1;
            }
        }
        return;
    }

    if (y >= 2) {    // K or V: plain fp16
        __half* Oh = (y < 4 ? g_kh : g_vh)
                   + ((size_t)z * HID + mBlk - (y < 4 ? 256 : 512)) * Nn;
        #pragma unroll
        for (int fm = 0; fm < 4; fm++) {
            int row = wm + fm * 16 + (lane >> 2);
            #pragma unroll
            for (int fn = 0; fn < 4; fn++) {
                int col = nBlk + wn + fn * 8 + (lane & 3) * 2;
                *(half2*)&Oh[(size_t)row * Nn + col] =
                    __halves2half2(__float2half_rn(acc[fm][fn][0]),
                                   __float2half_rn(acc[fm][fn][1]));
                *(half2*)&Oh[(size_t)(row + 8) * Nn + col] =
                    __halves2half2(__float2half_rn(acc[fm][fn][2]),
                                   __float2half_rn(acc[fm][fn][3]));
            }
        }
        return;
    }

    // Q: fused softmax over d (2 heads per 128-row tile), x SCALE, fp16 out
    {
        float* S    = (float*)smem;                       // [128][132]
        float* cInv = (float*)(smem + 128 * 132 * 4);     // [256]
        __syncthreads();
        #pragma unroll
        for (int fm = 0; fm < 4; fm++) {
            int row = wm + fm * 16 + (lane >> 2);
            #pragma unroll
            for (int fn = 0; fn < 4; fn++) {
                int col = wn + fn * 8 + (lane & 3) * 2;
                *(float2*)&S[row * 132 + col]       = make_float2(acc[fm][fn][0], acc[fm][fn][1]);
                *(float2*)&S[(row + 8) * 132 + col] = make_float2(acc[fm][fn][2], acc[fm][fn][3]);
            }
        }
        __syncthreads();

        {
            int colI = tid & 127;
            int hf   = tid >> 7;
            float mx = -INFINITY;
            #pragma unroll 4
            for (int r = 0; r < 64; r++)
                mx = fmaxf(mx, S[(hf * 64 + r) * 132 + colI]);
            float sum = 0.f;
            #pragma unroll 4
            for (int r = 0; r < 64; r++) {
                float e = __expf(S[(hf * 64 + r) * 132 + colI] - mx);
                S[(hf * 64 + r) * 132 + colI] = e;
                sum += e;
            }
            cInv[tid] = SCALE / sum;
        }
        __syncthreads();

        __half* Qh = g_qh + ((size_t)z * HID + mBlk) * Nn + nBlk;
        int c2   = (tid & 63) * 2;
        int rgrp = tid >> 6;
        #pragma unroll 4
        for (int rr = 0; rr < 32; rr++) {
            int row = rgrp * 32 + rr;
            int ci  = ((row >> 6) << 7) | c2;
            float2 v = *(float2*)&S[row * 132 + c2];
            *(half2*)&Qh[(size_t)row * Nn + c2] =
                __halves2half2(__float2half_rn(v.x * cInv[ci]),
                               __float2half_rn(v.y * cInv[ci + 1]));
        }
    }
}

// ===========================================================================
// Softmax over n on k: fp16 in/out, vectorized uint4 (8 halves per access).
// One block (256 thr) per (b,hd) row; 16 values per thread.
// ===========================================================================
__global__ void softmax_k_kernel()
{
    int row = blockIdx.x;
    size_t base = (size_t)row * Nn;
    __shared__ float red[256];
    const int tid = threadIdx.x;

    uint4 u[2];
    float v[16];
    float mx = -INFINITY;
    #pragma unroll
    for (int i = 0; i < 2; i++) {
        u[i] = *(const uint4*)(g_kh + base + (size_t)(tid + i * 256) * 8);
        const __half2* hp = (const __half2*)&u[i];
        #pragma unroll
        for (int j = 0; j < 4; j++) {
            float2 f = __half22float2(hp[j]);
            v[i * 8 + j * 2]     = f.x;
            v[i * 8 + j * 2 + 1] = f.y;
        }
    }
    #pragma unroll
    for (int i = 0; i < 16; i++) mx = fmaxf(mx, v[i]);

    red[tid] = mx; __syncthreads();
    for (int s = 128; s > 0; s >>= 1) { if (tid < s) red[tid] = fmaxf(red[tid], red[tid + s]); __syncthreads(); }
    mx = red[0]; __syncthreads();

    float sum = 0.f;
    #pragma unroll
    for (int i = 0; i < 16; i++) { v[i] = __expf(v[i] - mx); sum += v[i]; }
    red[tid] = sum; __syncthreads();
    for (int s = 128; s > 0; s >>= 1) { if (tid < s) red[tid] += red[tid + s]; __syncthreads(); }
    float inv = 1.f / red[0];

    #pragma unroll
    for (int i = 0; i < 2; i++) {
        __half2* hp = (__half2*)&u[i];
        #pragma unroll
        for (int j = 0; j < 4; j++)
            hp[j] = __floats2half2_rn(v[i * 8 + j * 2] * inv, v[i * 8 + j * 2 + 1] * inv);
        *(uint4*)(g_kh + base + (size_t)(tid + i * 256) * 8) = u[i];
    }
}

// ===========================================================================
// Context partials (16 n-chunks of 256): ctxp[bh][p][d][e] = sum k[d,n]v[e,n]
// fp16 x fp16 -> fp32.
// ===========================================================================
#define PK_B 272
#define CT_B (64 * PK_B)
#define CTX_SMEM_BYTES (2 * CT_B)     // 34816: kH, vH

__global__ void __launch_bounds__(128, 4)
context_part()
{
    extern __shared__ char smem[];
    const uint32_t sb = smem_u32(smem);
    int bh = blockIdx.x;
    int p  = blockIdx.y;
    int b = bh >> 2, h = bh & 3;
    const __half* Kh = g_kh + ((size_t)b * HID + h * Dd) * Nn;
    const __half* Vh = g_vh + ((size_t)b * HID + h * Dd) * Nn;

    const int tid  = threadIdx.x;
    const int wid  = tid >> 5;
    const int lane = tid & 31;
    const int wm = (wid >> 1) * 32;
    const int wn = (wid & 1) * 32;

    float acc[2][4][4];
    #pragma unroll
    for (int i = 0; i < 2; i++)
        #pragma unroll
        for (int j = 0; j < 4; j++)
            #pragma unroll
            for (int r = 0; r < 4; r++) acc[i][j][r] = 0.f;

    const int lr = lane & 15;
    const int lc = (lane >> 4) & 1;
    const uint32_t kHb = sb;
    const uint32_t vHb = kHb + CT_B;

    #pragma unroll 1
    for (int sl = 0; sl < 2; sl++) {
        const int nn = p * 256 + sl * 128;
        __syncthreads();
        #pragma unroll
        for (int q = 0; q < 8; q++) {
            int id = tid + q * 128;
            int row = id >> 4, ch = id & 15;
            size_t go = (size_t)row * Nn + nn + ch * 8;
            uint32_t off = row * PK_B + ch * 16;
            CP_ASYNC16(kHb + off, Kh + go);
            CP_ASYNC16(vHb + off, Vh + go);
        }
        CP_COMMIT();
        CP_WAIT(0);
        __syncthreads();

        #pragma unroll
        for (int ks = 0; ks < 8; ks++) {
            uint32_t bhf[2][4];
            #pragma unroll
            for (int fnp = 0; fnp < 2; fnp++) {
                uint32_t off = (uint32_t)(wn + fnp * 16 + lc * 8 + (lane & 7)) * PK_B
                             + (uint32_t)(ks * 32 + ((lane >> 3) & 1) * 16);
                LDM_X4(bhf[fnp], vHb + off);
            }
            #pragma unroll
            for (int fm = 0; fm < 2; fm++) {
                uint32_t off = (uint32_t)(wm + fm * 16 + lr) * PK_B
                             + (uint32_t)(ks * 32 + lc * 16);
                uint32_t ah[4];
                LDM_X4(ah, kHb + off);
                #pragma unroll
                for (int fn = 0; fn < 4; fn++)
                    mma16(acc[fm][fn], ah, &bhf[fn >> 1][(fn & 1) * 2]);
            }
        }
    }

    float* dst = g_ctxp + ((size_t)bh * 16 + p) * (Dd * Dd);
    #pragma unroll
    for (int fm = 0; fm < 2; fm++) {
        int d0 = wm + fm * 16 + (lane >> 2);
        #pragma unroll
        for (int fn = 0; fn < 4; fn++) {
            int e0 = wn + fn * 8 + (lane & 3) * 2;
            dst[d0 * Dd + e0]           = acc[fm][fn][0];
            dst[d0 * Dd + e0 + 1]       = acc[fm][fn][1];
            dst[(d0 + 8) * Dd + e0]     = acc[fm][fn][2];
            dst[(d0 + 8) * Dd + e0 + 1] = acc[fm][fn][3];
        }
    }
}

// ===========================================================================
// W2[b][c][h*64+d] = sum_e w_out[c][h*64+e] * ctx[bh][d][e]; fp16 out.
// ===========================================================================
__global__ void w2_kernel(const float* __restrict__ w_out)
{
    int bh = blockIdx.x;
    int b = bh >> 2, h = bh & 3;
    __shared__ float ctx[Dd * Dd];
    const int tid = threadIdx.x;

    for (int i = tid; i < Dd * Dd; i += 256) {
        float s = 0.f;
        #pragma unroll
        for (int p = 0; p < 16; p++)
            s += g_ctxp[((size_t)bh * 16 + p) * (Dd * Dd) + i];
        ctx[i] = s;
    }
    __syncthreads();

    int c = tid;
    float w[Dd];
    #pragma unroll
    for (int e = 0; e < Dd; e++) w[e] = w_out[c * HID + h * Dd + e];
    #pragma unroll 4
    for (int d = 0; d < Dd; d++) {
        float s = 0.f;
        #pragma unroll
        for (int e = 0; e < Dd; e++) s = fmaf(w[e], ctx[d * Dd + e], s);
        g_w2h[((size_t)b * HID + c) * HID + h * Dd + d] = __float2half_rn(s);
    }
}

// ===========================================================================
extern "C" void kernel_launch(void* const* d_in, const int* in_sizes, int n_in,
                              void* d_out, int out_size)
{
    const float* x     = (const float*)d_in[0];
    const float* w_qkv = (const float*)d_in[1];
    const float* w_out = (const float*)d_in[2];
    const float* b_out = (const float*)d_in[3];
    float* out = (float*)d_out;

    __half *xh, *wh, *qh, *w2h;
    cudaGetSymbolAddress((void**)&xh, g_xh);
    cudaGetSymbolAddress((void**)&wh, g_wh);
    cudaGetSymbolAddress((void**)&qh, g_qh);
    cudaGetSymbolAddress((void**)&w2h, g_w2h);

    static int init_done = 0;
    static cudaStream_t s2;
    static cudaEvent_t evKV, evW2;
    if (!init_done) {
        cudaFuncSetAttribute(fused_gemm, cudaFuncAttributeMaxDynamicSharedMemorySize, FG_SMEM);
        cudaFuncSetAttribute(context_part, cudaFuncAttributeMaxDynamicSharedMemorySize, CTX_SMEM_BYTES);
        cudaStreamCreateWithFlags(&s2, cudaStreamNonBlocking);
        cudaEventCreateWithFlags(&evKV, cudaEventDisableTiming);
        cudaEventCreateWithFlags(&evW2, cudaEventDisableTiming);
        init_done = 1;
    }

    // 0) x, w_qkv -> fp16
    {
        int n4 = (Bn * Cc * Nn) / 4;
        half_kernel<<<(n4 + 255) / 256, 256>>>(x, xh, n4);
        int w4 = (O3 * Cc) / 4;
        half_kernel<<<(w4 + 255) / 256, 256>>>(w_qkv, wh, w4);
    }

    // 1a) GEMM1 K+V sections (y = 2..5)
    {
        dim3 grid(Nn / 128, 4, Bn);
        fused_gemm<<<grid, 256, FG_SMEM>>>(wh, 0, xh, (size_t)Cc * Nn,
                                           0, 2, nullptr, nullptr);
    }
    cudaEventRecord(evKV, 0);

    // 1b) GEMM1 Q section (y = 0..1), overlaps the k-chain on s2
    {
        dim3 grid(Nn / 128, 2, Bn);
        fused_gemm<<<grid, 256, FG_SMEM>>>(wh, 0, xh, (size_t)Cc * Nn,
                                           0, 0, nullptr, nullptr);
    }

    // side stream: softmax_k -> context -> w2
    cudaStreamWaitEvent(s2, evKV, 0);
    softmax_k_kernel<<<Bn * HID, 256, 0, s2>>>();
    {
        dim3 gridc(Bn * Hh, 16);
        context_part<<<gridc, 128, CTX_SMEM_BYTES, s2>>>();
    }
    w2_kernel<<<Bn * Hh, 256, 0, s2>>>(w_out);
    cudaEventRecord(evW2, s2);

    // 2) GEMM2 after q (main stream order) and w2 (event)
    cudaStreamWaitEvent(0, evW2, 0);
    {
        dim3 grid2(Nn / 128, HID / 128, Bn);
        fused_gemm<<<grid2, 256, FG_SMEM>>>(w2h, (size_t)HID * HID,
                                            qh, (size_t)HID * Nn,
                                            1, 0, b_out, out);
    }
}

// round 15
// speedup vs baseline: 1.9703x; 1.0211x over previous
#include <cuda_runtime.h>
#include <cuda_fp16.h>
#include <math.h>
#include <stdint.h>

// Problem constants
#define Bn   16
#define Cc   256
#define Nn   4096
#define Hh   4
#define Dd   64
#define O3   768
#define HID  256
#define SCALE 0.125f

// Scratch (pure fp16 operand pipeline, fp32 accumulation everywhere)
__device__ __half g_xh[(size_t)Bn * Cc * Nn];     // x fp16
__device__ __half g_wh[O3 * Cc];                  // w_qkv fp16
__device__ __half g_qh[(size_t)Bn * HID * Nn];    // q softmaxed fp16
__device__ __half g_kh[(size_t)Bn * HID * Nn];    // k fp16 (softmaxed in place)
__device__ __half g_vh[(size_t)Bn * HID * Nn];    // v fp16
__device__ float  g_ctxp[(size_t)Bn * Hh * 16 * Dd * Dd];
__device__ __half g_w2h[(size_t)Bn * HID * HID];  // w_out @ ctx^T fp16

// ===========================================================================
// Helpers
// ===========================================================================
__device__ __forceinline__ uint32_t smem_u32(const void* p) {
    uint32_t a;
    asm("{ .reg .u64 t; cvta.to.shared.u64 t, %1; cvt.u32.u64 %0, t; }" : "=r"(a) : "l"(p));
    return a;
}
__device__ __forceinline__ void mma16(float* d, const uint32_t* a, const uint32_t* b) {
    asm volatile(
        "mma.sync.aligned.m16n8k16.row.col.f32.f16.f16.f32 "
        "{%0,%1,%2,%3},{%4,%5,%6,%7},{%8,%9},{%0,%1,%2,%3};"
        : "+f"(d[0]), "+f"(d[1]), "+f"(d[2]), "+f"(d[3])
        : "r"(a[0]), "r"(a[1]), "r"(a[2]), "r"(a[3]), "r"(b[0]), "r"(b[1]));
}
#define LDM_X4(r, addr) \
    asm volatile("ldmatrix.sync.aligned.m8n8.x4.shared.b16 {%0,%1,%2,%3}, [%4];" \
        : "=r"((r)[0]), "=r"((r)[1]), "=r"((r)[2]), "=r"((r)[3]) : "r"(addr))
#define LDM_X4_T(r, addr) \
    asm volatile("ldmatrix.sync.aligned.m8n8.x4.trans.shared.b16 {%0,%1,%2,%3}, [%4];" \
        : "=r"((r)[0]), "=r"((r)[1]), "=r"((r)[2]), "=r"((r)[3]) : "r"(addr))
#define CP_ASYNC16(dst, src) \
    asm volatile("cp.async.cg.shared.global [%0], [%1], 16;" :: "r"(dst), "l"(src))
#define CP_COMMIT() asm volatile("cp.async.commit_group;" ::: "memory")
#define CP_WAIT(n)  asm volatile("cp.async.wait_group %0;" :: "n"(n) : "memory")

// ===========================================================================
// fp32 -> fp16 conversion
// ===========================================================================
__global__ void half_kernel(const float* __restrict__ src, __half* __restrict__ h, int n4)
{
    int i = blockIdx.x * blockDim.x + threadIdx.x;
    if (i >= n4) return;
    float4 v = *(const float4*)(src + (size_t)i * 4);
    *(half2*)(h + (size_t)i * 4)     = __halves2half2(__float2half_rn(v.x), __float2half_rn(v.y));
    *(half2*)(h + (size_t)i * 4 + 2) = __halves2half2(__float2half_rn(v.z), __float2half_rn(v.w));
}

// ===========================================================================
// fused_gemm: plain fp16 GEMM, fp32 accumulate.
// C = A x B, K=256, BK=64 (4 slices), 2-stage cp.async, 2 CTAs/SM.
// Tile 128x128, 8 warps = 2m x 4n (warp 64x32).
// compute(): all A fragments per ks hoisted into ah[4][4] before the MMA
// burst -> 6 pipelined LDSMs then 16 back-to-back MMAs (breaks LDSM->MMA
// serialization that capped tensor pipe at 32%).
// mode 0 (GEMM1): y 0-1 q (fused softmax_d -> fp16), y 2-3 k, y 4-5 v.
// mode 1 (GEMM2): fp32 out + bias.
// ===========================================================================
#define PA_B 144                     // A pitch bytes (64 halves + 16 pad)
#define PB_B 272                     // B pitch bytes (128 halves + 16 pad)
#define A_ST (128 * PA_B)            // 18432
#define B_ST (64 * PB_B)             // 17408
#define STG  (A_ST + B_ST)           // 35840
#define FG_SMEM (2 * STG)            // 71680 -> 2 CTAs/SM

__global__ void __launch_bounds__(256, 2)
fused_gemm(const __half* __restrict__ Ah, size_t aStride,
           const __half* __restrict__ Bh, size_t bStride,
           int mode, const float* __restrict__ bias, float* __restrict__ outF)
{
    extern __shared__ char smem[];
    const uint32_t sb = smem_u32(smem);
    const int tid  = threadIdx.x;
    const int wid  = tid >> 5;
    const int lane = tid & 31;
    const int wm   = (wid >> 2) * 64;
    const int wn   = (wid & 3) * 32;
    const int y    = blockIdx.y;
    const int mBlk = y * 128;
    const int nBlk = blockIdx.x * 128;
    const int z    = blockIdx.z;

    const __half* Ag = Ah + (size_t)z * aStride + (size_t)mBlk * 256;
    const __half* Bg = Bh + (size_t)z * bStride + nBlk;

    float acc[4][4][4];
    #pragma unroll
    for (int i = 0; i < 4; i++)
        #pragma unroll
        for (int j = 0; j < 4; j++)
            #pragma unroll
            for (int r = 0; r < 4; r++) acc[i][j][r] = 0.f;

    auto issue = [&](int s, int buf) {
        const int kk = s * 64;
        const uint32_t st = sb + buf * STG;
        #pragma unroll
        for (int p = 0; p < 4; p++) {            // A: 128 rows x 8 chunks
            int id = tid + p * 256;
            int m = id >> 3, ch = id & 7;
            size_t go = (size_t)m * 256 + kk + ch * 8;
            CP_ASYNC16(st + m * PA_B + ch * 16, Ag + go);
        }
        #pragma unroll
        for (int p = 0; p < 4; p++) {            // B: 64 rows x 16 chunks
            int id = tid + p * 256;
            int r = id >> 4, ch = id & 15;
            size_t go = (size_t)(kk + r) * Nn + ch * 8;
            CP_ASYNC16(st + A_ST + r * PB_B + ch * 16, Bg + go);
        }
    };

    const int lr = lane & 15;
    const int lc = (lane >> 4) & 1;

    auto compute = [&](int buf) {
        const uint32_t aHb = sb + buf * STG;
        const uint32_t bHb = aHb + A_ST;
        #pragma unroll
        for (int ks = 0; ks < 4; ks++) {
            uint32_t bh[2][4];
            #pragma unroll
            for (int fnp = 0; fnp < 2; fnp++) {
                uint32_t off = (uint32_t)(ks * 16 + lr) * PB_B
                             + (uint32_t)(wn + fnp * 16 + lc * 8) * 2;
                LDM_X4_T(bh[fnp], bHb + off);
            }
            uint32_t ah[4][4];
            #pragma unroll
            for (int fm = 0; fm < 4; fm++) {
                uint32_t off = (uint32_t)(wm + fm * 16 + lr) * PA_B
                             + (uint32_t)(ks * 16 + lc * 8) * 2;
                LDM_X4(ah[fm], aHb + off);
            }
            #pragma unroll
            for (int fm = 0; fm < 4; fm++)
                #pragma unroll
                for (int fn = 0; fn < 4; fn++)
                    mma16(acc[fm][fn], ah[fm], &bh[fn >> 1][(fn & 1) * 2]);
        }
    };

    issue(0, 0); CP_COMMIT();
    issue(1, 1); CP_COMMIT();
    #pragma unroll 1
    for (int s = 0; s < 4; s++) {
        if (s < 3) { CP_WAIT(1); } else { CP_WAIT(0); }
        __syncthreads();
        compute(s & 1);
        if (s + 2 < 4) {
            __syncthreads();
            issue(s + 2, s & 1); CP_COMMIT();
        }
    }

    // ------------------------------ epilogues ------------------------------
    if (mode == 1) {
        float* Cg = outF + (size_t)z * HID * Nn;
        #pragma unroll
        for (int fm = 0; fm < 4; fm++) {
            int row = mBlk + wm + fm * 16 + (lane >> 2);
            float b0 = bias[row], b8 = bias[row + 8];
            #pragma unroll
            for (int fn = 0; fn < 4; fn++) {
                int col = nBlk + wn + fn * 8 + (lane & 3) * 2;
                float2 v0 = { acc[fm][fn][0] + b0, acc[fm][fn][1] + b0 };
                float2 v1 = { acc[fm][fn][2] + b8, acc[fm][fn][3] + b8 };
                *(float2*)&Cg[(size_t)row * Nn + col]       = v0;
                *(float2*)&Cg[(size_t)(row + 8) * Nn + col] = v1;
            }
        }
        return;
    }

    if (y >= 2) {    // K or V: plain fp16
        __half* Oh = (y < 4 ? g_kh : g_vh)
                   + ((size_t)z * HID + mBlk - (y < 4 ? 256 : 512)) * Nn;
        #pragma unroll
        for (int fm = 0; fm < 4; fm++) {
            int row = wm + fm * 16 + (lane >> 2);
            #pragma unroll
            for (int fn = 0; fn < 4; fn++) {
                int col = nBlk + wn + fn * 8 + (lane & 3) * 2;
                *(half2*)&Oh[(size_t)row * Nn + col] =
                    __halves2half2(__float2half_rn(acc[fm][fn][0]),
                                   __float2half_rn(acc[fm][fn][1]));
                *(half2*)&Oh[(size_t)(row + 8) * Nn + col] =
                    __halves2half2(__float2half_rn(acc[fm][fn][2]),
                                   __float2half_rn(acc[fm][fn][3]));
            }
        }
        return;
    }

    // Q: fused softmax over d (2 heads per 128-row tile), x SCALE, fp16 out
    {
        float* S    = (float*)smem;                       // [128][132]
        float* cInv = (float*)(smem + 128 * 132 * 4);     // [256]
        __syncthreads();
        #pragma unroll
        for (int fm = 0; fm < 4; fm++) {
            int row = wm + fm * 16 + (lane >> 2);
            #pragma unroll
            for (int fn = 0; fn < 4; fn++) {
                int col = wn + fn * 8 + (lane & 3) * 2;
                *(float2*)&S[row * 132 + col]       = make_float2(acc[fm][fn][0], acc[fm][fn][1]);
                *(float2*)&S[(row + 8) * 132 + col] = make_float2(acc[fm][fn][2], acc[fm][fn][3]);
            }
        }
        __syncthreads();

        {
            int colI = tid & 127;
            int hf   = tid >> 7;
            float mx = -INFINITY;
            #pragma unroll 4
            for (int r = 0; r < 64; r++)
                mx = fmaxf(mx, S[(hf * 64 + r) * 132 + colI]);
            float sum = 0.f;
            #pragma unroll 4
            for (int r = 0; r < 64; r++) {
                float e = __expf(S[(hf * 64 + r) * 132 + colI] - mx);
                S[(hf * 64 + r) * 132 + colI] = e;
                sum += e;
            }
            cInv[tid] = SCALE / sum;
        }
        __syncthreads();

        __half* Qh = g_qh + ((size_t)z * HID + mBlk) * Nn + nBlk;
        int c2   = (tid & 63) * 2;
        int rgrp = tid >> 6;
        #pragma unroll 4
        for (int rr = 0; rr < 32; rr++) {
            int row = rgrp * 32 + rr;
            int ci  = ((row >> 6) << 7) | c2;
            float2 v = *(float2*)&S[row * 132 + c2];
            *(half2*)&Qh[(size_t)row * Nn + c2] =
                __halves2half2(__float2half_rn(v.x * cInv[ci]),
                               __float2half_rn(v.y * cInv[ci + 1]));
        }
    }
}

// ===========================================================================
// Softmax over n on k: fp16 in/out, vectorized uint4 (8 halves per access).
// ===========================================================================
__global__ void softmax_k_kernel()
{
    int row = blockIdx.x;
    size_t base = (size_t)row * Nn;
    __shared__ float red[256];
    const int tid = threadIdx.x;

    uint4 u[2];
    float v[16];
    float mx = -INFINITY;
    #pragma unroll
    for (int i = 0; i < 2; i++) {
        u[i] = *(const uint4*)(g_kh + base + (size_t)(tid + i * 256) * 8);
        const __half2* hp = (const __half2*)&u[i];
        #pragma unroll
        for (int j = 0; j < 4; j++) {
            float2 f = __half22float2(hp[j]);
            v[i * 8 + j * 2]     = f.x;
            v[i * 8 + j * 2 + 1] = f.y;
        }
    }
    #pragma unroll
    for (int i = 0; i < 16; i++) mx = fmaxf(mx, v[i]);

    red[tid] = mx; __syncthreads();
    for (int s = 128; s > 0; s >>= 1) { if (tid < s) red[tid] = fmaxf(red[tid], red[tid + s]); __syncthreads(); }
    mx = red[0]; __syncthreads();

    float sum = 0.f;
    #pragma unroll
    for (int i = 0; i < 16; i++) { v[i] = __expf(v[i] - mx); sum += v[i]; }
    red[tid] = sum; __syncthreads();
    for (int s = 128; s > 0; s >>= 1) { if (tid < s) red[tid] += red[tid + s]; __syncthreads(); }
    float inv = 1.f / red[0];

    #pragma unroll
    for (int i = 0; i < 2; i++) {
        __half2* hp = (__half2*)&u[i];
        #pragma unroll
        for (int j = 0; j < 4; j++)
            hp[j] = __floats2half2_rn(v[i * 8 + j * 2] * inv, v[i * 8 + j * 2 + 1] * inv);
        *(uint4*)(g_kh + base + (size_t)(tid + i * 256) * 8) = u[i];
    }
}

// ===========================================================================
// Context partials (16 n-chunks of 256): ctxp[bh][p][d][e] = sum k[d,n]v[e,n]
// fp16 x fp16 -> fp32. A-fragments hoisted (same fix as fused_gemm).
// ===========================================================================
#define PK_B 272
#define CT_B (64 * PK_B)
#define CTX_SMEM_BYTES (2 * CT_B)     // 34816: kH, vH

__global__ void __launch_bounds__(128, 4)
context_part()
{
    extern __shared__ char smem[];
    const uint32_t sb = smem_u32(smem);
    int bh = blockIdx.x;
    int p  = blockIdx.y;
    int b = bh >> 2, h = bh & 3;
    const __half* Kh = g_kh + ((size_t)b * HID + h * Dd) * Nn;
    const __half* Vh = g_vh + ((size_t)b * HID + h * Dd) * Nn;

    const int tid  = threadIdx.x;
    const int wid  = tid >> 5;
    const int lane = tid & 31;
    const int wm = (wid >> 1) * 32;
    const int wn = (wid & 1) * 32;

    float acc[2][4][4];
    #pragma unroll
    for (int i = 0; i < 2; i++)
        #pragma unroll
        for (int j = 0; j < 4; j++)
            #pragma unroll
            for (int r = 0; r < 4; r++) acc[i][j][r] = 0.f;

    const int lr = lane & 15;
    const int lc = (lane >> 4) & 1;
    const uint32_t kHb = sb;
    const uint32_t vHb = kHb + CT_B;

    #pragma unroll 1
    for (int sl = 0; sl < 2; sl++) {
        const int nn = p * 256 + sl * 128;
        __syncthreads();
        #pragma unroll
        for (int q = 0; q < 8; q++) {
            int id = tid + q * 128;
            int row = id >> 4, ch = id & 15;
            size_t go = (size_t)row * Nn + nn + ch * 8;
            uint32_t off = row * PK_B + ch * 16;
            CP_ASYNC16(kHb + off, Kh + go);
            CP_ASYNC16(vHb + off, Vh + go);
        }
        CP_COMMIT();
        CP_WAIT(0);
        __syncthreads();

        #pragma unroll
        for (int ks = 0; ks < 8; ks++) {
            uint32_t bhf[2][4];
            #pragma unroll
            for (int fnp = 0; fnp < 2; fnp++) {
                uint32_t off = (uint32_t)(wn + fnp * 16 + lc * 8 + (lane & 7)) * PK_B
                             + (uint32_t)(ks * 32 + ((lane >> 3) & 1) * 16);
                LDM_X4(bhf[fnp], vHb + off);
            }
            uint32_t ah[2][4];
            #pragma unroll
            for (int fm = 0; fm < 2; fm++) {
                uint32_t off = (uint32_t)(wm + fm * 16 + lr) * PK_B
                             + (uint32_t)(ks * 32 + lc * 16);
                LDM_X4(ah[fm], kHb + off);
            }
            #pragma unroll
            for (int fm = 0; fm < 2; fm++)
                #pragma unroll
                for (int fn = 0; fn < 4; fn++)
                    mma16(acc[fm][fn], ah[fm], &bhf[fn >> 1][(fn & 1) * 2]);
        }
    }

    float* dst = g_ctxp + ((size_t)bh * 16 + p) * (Dd * Dd);
    #pragma unroll
    for (int fm = 0; fm < 2; fm++) {
        int d0 = wm + fm * 16 + (lane >> 2);
        #pragma unroll
        for (int fn = 0; fn < 4; fn++) {
            int e0 = wn + fn * 8 + (lane & 3) * 2;
            dst[d0 * Dd + e0]           = acc[fm][fn][0];
            dst[d0 * Dd + e0 + 1]       = acc[fm][fn][1];
            dst[(d0 + 8) * Dd + e0]     = acc[fm][fn][2];
            dst[(d0 + 8) * Dd + e0 + 1] = acc[fm][fn][3];
        }
    }
}

// ===========================================================================
// W2[b][c][h*64+d] = sum_e w_out[c][h*64+e] * ctx[bh][d][e]; fp16 out.
// ===========================================================================
__global__ void w2_kernel(const float* __restrict__ w_out)
{
    int bh = blockIdx.x;
    int b = bh >> 2, h = bh & 3;
    __shared__ float ctx[Dd * Dd];
    const int tid = threadIdx.x;

    for (int i = tid; i < Dd * Dd; i += 256) {
        float s = 0.f;
        #pragma unroll
        for (int p = 0; p < 16; p++)
            s += g_ctxp[((size_t)bh * 16 + p) * (Dd * Dd) + i];
        ctx[i] = s;
    }
    __syncthreads();

    int c = tid;
    float w[Dd];
    #pragma unroll
    for (int e = 0; e < Dd; e++) w[e] = w_out[c * HID + h * Dd + e];
    #pragma unroll 4
    for (int d = 0; d < Dd; d++) {
        float s = 0.f;
        #pragma unroll
        for (int e = 0; e < Dd; e++) s = fmaf(w[e], ctx[d * Dd + e], s);
        g_w2h[((size_t)b * HID + c) * HID + h * Dd + d] = __float2half_rn(s);
    }
}

// ===========================================================================
extern "C" void kernel_launch(void* const* d_in, const int* in_sizes, int n_in,
                              void* d_out, int out_size)
{
    const float* x     = (const float*)d_in[0];
    const float* w_qkv = (const float*)d_in[1];
    const float* w_out = (const float*)d_in[2];
    const float* b_out = (const float*)d_in[3];
    float* out = (float*)d_out;

    __half *xh, *wh, *qh, *w2h;
    cudaGetSymbolAddress((void**)&xh, g_xh);
    cudaGetSymbolAddress((void**)&wh, g_wh);
    cudaGetSymbolAddress((void**)&qh, g_qh);
    cudaGetSymbolAddress((void**)&w2h, g_w2h);

    static int init_done = 0;
    if (!init_done) {
        cudaFuncSetAttribute(fused_gemm, cudaFuncAttributeMaxDynamicSharedMemorySize, FG_SMEM);
        cudaFuncSetAttribute(context_part, cudaFuncAttributeMaxDynamicSharedMemorySize, CTX_SMEM_BYTES);
        init_done = 1;
    }

    // 0) x, w_qkv -> fp16
    {
        int n4 = (Bn * Cc * Nn) / 4;
        half_kernel<<<(n4 + 255) / 256, 256>>>(x, xh, n4);
        int w4 = (O3 * Cc) / 4;
        half_kernel<<<(w4 + 255) / 256, 256>>>(w_qkv, wh, w4);
    }
    // 1) GEMM1: single launch, y selects q/k/v epilogue
    {
        dim3 grid(Nn / 128, O3 / 128, Bn);
        fused_gemm<<<grid, 256, FG_SMEM>>>(wh, 0, xh, (size_t)Cc * Nn,
                                           0, nullptr, nullptr);
    }
    // 2) softmax over n on k (in place, fp16)
    softmax_k_kernel<<<Bn * HID, 256>>>();
    // 3) context partials
    {
        dim3 gridc(Bn * Hh, 16);
        context_part<<<gridc, 128, CTX_SMEM_BYTES>>>();
    }
    // 4) W2
    w2_kernel<<<Bn * Hh, 256>>>(w_out);
    // 5) GEMM2: out = W2 @ q + bias
    {
        dim3 grid2(Nn / 128, HID / 128, Bn);
        fused_gemm<<<grid2, 256, FG_SMEM>>>(w2h, (size_t)HID * HID,
                                            qh, (size_t)HID * Nn,
                                            1, b_out, out);
    }
}

// round 16
// speedup vs baseline: 1.9806x; 1.0052x over previous
#include <cuda_runtime.h>
#include <cuda_fp16.h>
#include <math.h>
#include <stdint.h>

// Problem constants
#define Bn   16
#define Cc   256
#define Nn   4096
#define Hh   4
#define Dd   64
#define O3   768
#define HID  256
#define SCALE 0.125f

// Scratch (pure fp16 operand pipeline, fp32 accumulation everywhere)
__device__ __half g_xh[(size_t)Bn * Cc * Nn];     // x fp16
__device__ __half g_wh[O3 * Cc];                  // w_qkv fp16
__device__ __half g_qh[(size_t)Bn * HID * Nn];    // q softmaxed fp16
__device__ __half g_kh[(size_t)Bn * HID * Nn];    // k fp16 (softmaxed in place)
__device__ __half g_vh[(size_t)Bn * HID * Nn];    // v fp16
__device__ float  g_ctxp[(size_t)Bn * Hh * 16 * Dd * Dd];
__device__ __half g_w2h[(size_t)Bn * HID * HID];  // w_out @ ctx^T fp16

// ===========================================================================
// Helpers
// ===========================================================================
__device__ __forceinline__ uint32_t smem_u32(const void* p) {
    uint32_t a;
    asm("{ .reg .u64 t; cvta.to.shared.u64 t, %1; cvt.u32.u64 %0, t; }" : "=r"(a) : "l"(p));
    return a;
}
__device__ __forceinline__ void mma16(float* d, const uint32_t* a, const uint32_t* b) {
    asm volatile(
        "mma.sync.aligned.m16n8k16.row.col.f32.f16.f16.f32 "
        "{%0,%1,%2,%3},{%4,%5,%6,%7},{%8,%9},{%0,%1,%2,%3};"
        : "+f"(d[0]), "+f"(d[1]), "+f"(d[2]), "+f"(d[3])
        : "r"(a[0]), "r"(a[1]), "r"(a[2]), "r"(a[3]), "r"(b[0]), "r"(b[1]));
}
#define LDM_X4(r, addr) \
    asm volatile("ldmatrix.sync.aligned.m8n8.x4.shared.b16 {%0,%1,%2,%3}, [%4];" \
        : "=r"((r)[0]), "=r"((r)[1]), "=r"((r)[2]), "=r"((r)[3]) : "r"(addr))
#define LDM_X4_T(r, addr) \
    asm volatile("ldmatrix.sync.aligned.m8n8.x4.trans.shared.b16 {%0,%1,%2,%3}, [%4];" \
        : "=r"((r)[0]), "=r"((r)[1]), "=r"((r)[2]), "=r"((r)[3]) : "r"(addr))
#define CP_ASYNC16(dst, src) \
    asm volatile("cp.async.cg.shared.global [%0], [%1], 16;" :: "r"(dst), "l"(src))
#define CP_COMMIT() asm volatile("cp.async.commit_group;" ::: "memory")
#define CP_WAIT(n)  asm volatile("cp.async.wait_group %0;" :: "n"(n) : "memory")

// ===========================================================================
// fp32 -> fp16 conversion
// ===========================================================================
__global__ void half_kernel(const float* __restrict__ src, __half* __restrict__ h, int n4)
{
    int i = blockIdx.x * blockDim.x + threadIdx.x;
    if (i >= n4) return;
    float4 v = *(const float4*)(src + (size_t)i * 4);
    *(half2*)(h + (size_t)i * 4)     = __halves2half2(__float2half_rn(v.x), __float2half_rn(v.y));
    *(half2*)(h + (size_t)i * 4 + 2) = __halves2half2(__float2half_rn(v.z), __float2half_rn(v.w));
}

// ===========================================================================
// fused_gemm: plain fp16 GEMM, fp32 accumulate.
// C = A x B, K=256, BK=64 (4 slices), 3-stage cp.async ring, ONE barrier
// per slice (issue s+2 before compute(s); buffer (s+2)%3 readers finished
// at the post-wait barrier). 2 CTAs/SM. Tile 128x128, 8 warps = 2m x 4n.
// mode 0 (GEMM1): y 0-1 q (fused softmax_d -> fp16), y 2-3 k, y 4-5 v.
// mode 1 (GEMM2): fp32 out + bias.
// ===========================================================================
#define PA_B 144                     // A pitch bytes (64 halves + 16 pad)
#define PB_B 272                     // B pitch bytes (128 halves + 16 pad)
#define A_ST (128 * PA_B)            // 18432
#define B_ST (64 * PB_B)             // 17408
#define STG  (A_ST + B_ST)           // 35840
#define FG_SMEM (3 * STG)            // 107520 -> 2 CTAs/SM (215 KB)

__global__ void __launch_bounds__(256, 2)
fused_gemm(const __half* __restrict__ Ah, size_t aStride,
           const __half* __restrict__ Bh, size_t bStride,
           int mode, const float* __restrict__ bias, float* __restrict__ outF)
{
    extern __shared__ char smem[];
    const uint32_t sb = smem_u32(smem);
    const int tid  = threadIdx.x;
    const int wid  = tid >> 5;
    const int lane = tid & 31;
    const int wm   = (wid >> 2) * 64;
    const int wn   = (wid & 3) * 32;
    const int y    = blockIdx.y;
    const int mBlk = y * 128;
    const int nBlk = blockIdx.x * 128;
    const int z    = blockIdx.z;

    const __half* Ag = Ah + (size_t)z * aStride + (size_t)mBlk * 256;
    const __half* Bg = Bh + (size_t)z * bStride + nBlk;

    float acc[4][4][4];
    #pragma unroll
    for (int i = 0; i < 4; i++)
        #pragma unroll
        for (int j = 0; j < 4; j++)
            #pragma unroll
            for (int r = 0; r < 4; r++) acc[i][j][r] = 0.f;

    auto issue = [&](int s, int buf) {
        const int kk = s * 64;
        const uint32_t st = sb + buf * STG;
        #pragma unroll
        for (int p = 0; p < 4; p++) {            // A: 128 rows x 8 chunks
            int id = tid + p * 256;
            int m = id >> 3, ch = id & 7;
            size_t go = (size_t)m * 256 + kk + ch * 8;
            CP_ASYNC16(st + m * PA_B + ch * 16, Ag + go);
        }
        #pragma unroll
        for (int p = 0; p < 4; p++) {            // B: 64 rows x 16 chunks
            int id = tid + p * 256;
            int r = id >> 4, ch = id & 15;
            size_t go = (size_t)(kk + r) * Nn + ch * 8;
            CP_ASYNC16(st + A_ST + r * PB_B + ch * 16, Bg + go);
        }
    };

    const int lr = lane & 15;
    const int lc = (lane >> 4) & 1;

    auto compute = [&](int buf) {
        const uint32_t aHb = sb + buf * STG;
        const uint32_t bHb = aHb + A_ST;
        #pragma unroll
        for (int ks = 0; ks < 4; ks++) {
            uint32_t bh[2][4];
            #pragma unroll
            for (int fnp = 0; fnp < 2; fnp++) {
                uint32_t off = (uint32_t)(ks * 16 + lr) * PB_B
                             + (uint32_t)(wn + fnp * 16 + lc * 8) * 2;
                LDM_X4_T(bh[fnp], bHb + off);
            }
            uint32_t ah[4][4];
            #pragma unroll
            for (int fm = 0; fm < 4; fm++) {
                uint32_t off = (uint32_t)(wm + fm * 16 + lr) * PA_B
                             + (uint32_t)(ks * 16 + lc * 8) * 2;
                LDM_X4(ah[fm], aHb + off);
            }
            #pragma unroll
            for (int fm = 0; fm < 4; fm++)
                #pragma unroll
                for (int fn = 0; fn < 4; fn++)
                    mma16(acc[fm][fn], ah[fm], &bh[fn >> 1][(fn & 1) * 2]);
        }
    };

    issue(0, 0); CP_COMMIT();
    issue(1, 1); CP_COMMIT();
    #pragma unroll 1
    for (int s = 0; s < 4; s++) {
        if (s < 3) { CP_WAIT(1); } else { CP_WAIT(0); }
        __syncthreads();                  // group s ready AND compute(s-1) done
        if (s + 2 < 4) { issue(s + 2, (s + 2) % 3); CP_COMMIT(); }
        compute(s % 3);
    }

    // ------------------------------ epilogues ------------------------------
    if (mode == 1) {
        float* Cg = outF + (size_t)z * HID * Nn;
        #pragma unroll
        for (int fm = 0; fm < 4; fm++) {
            int row = mBlk + wm + fm * 16 + (lane >> 2);
            float b0 = bias[row], b8 = bias[row + 8];
            #pragma unroll
            for (int fn = 0; fn < 4; fn++) {
                int col = nBlk + wn + fn * 8 + (lane & 3) * 2;
                float2 v0 = { acc[fm][fn][0] + b0, acc[fm][fn][1] + b0 };
                float2 v1 = { acc[fm][fn][2] + b8, acc[fm][fn][3] + b8 };
                *(float2*)&Cg[(size_t)row * Nn + col]       = v0;
                *(float2*)&Cg[(size_t)(row + 8) * Nn + col] = v1;
            }
        }
        return;
    }

    if (y >= 2) {    // K or V: plain fp16
        __half* Oh = (y < 4 ? g_kh : g_vh)
                   + ((size_t)z * HID + mBlk - (y < 4 ? 256 : 512)) * Nn;
        #pragma unroll
        for (int fm = 0; fm < 4; fm++) {
            int row = wm + fm * 16 + (lane >> 2);
            #pragma unroll
            for (int fn = 0; fn < 4; fn++) {
                int col = nBlk + wn + fn * 8 + (lane & 3) * 2;
                *(half2*)&Oh[(size_t)row * Nn + col] =
                    __halves2half2(__float2half_rn(acc[fm][fn][0]),
                                   __float2half_rn(acc[fm][fn][1]));
                *(half2*)&Oh[(size_t)(row + 8) * Nn + col] =
                    __halves2half2(__float2half_rn(acc[fm][fn][2]),
                                   __float2half_rn(acc[fm][fn][3]));
            }
        }
        return;
    }

    // Q: fused softmax over d (2 heads per 128-row tile), x SCALE, fp16 out
    {
        float* S    = (float*)smem;                       // [128][132]
        float* cInv = (float*)(smem + 128 * 132 * 4);     // [256]
        __syncthreads();
        #pragma unroll
        for (int fm = 0; fm < 4; fm++) {
            int row = wm + fm * 16 + (lane >> 2);
            #pragma unroll
            for (int fn = 0; fn < 4; fn++) {
                int col = wn + fn * 8 + (lane & 3) * 2;
                *(float2*)&S[row * 132 + col]       = make_float2(acc[fm][fn][0], acc[fm][fn][1]);
                *(float2*)&S[(row + 8) * 132 + col] = make_float2(acc[fm][fn][2], acc[fm][fn][3]);
            }
        }
        __syncthreads();

        {
            int colI = tid & 127;
            int hf   = tid >> 7;
            float mx = -INFINITY;
            #pragma unroll 4
            for (int r = 0; r < 64; r++)
                mx = fmaxf(mx, S[(hf * 64 + r) * 132 + colI]);
            float sum = 0.f;
            #pragma unroll 4
            for (int r = 0; r < 64; r++) {
                float e = __expf(S[(hf * 64 + r) * 132 + colI] - mx);
                S[(hf * 64 + r) * 132 + colI] = e;
                sum += e;
            }
            cInv[tid] = SCALE / sum;
        }
        __syncthreads();

        __half* Qh = g_qh + ((size_t)z * HID + mBlk) * Nn + nBlk;
        int c2   = (tid & 63) * 2;
        int rgrp = tid >> 6;
        #pragma unroll 4
        for (int rr = 0; rr < 32; rr++) {
            int row = rgrp * 32 + rr;
            int ci  = ((row >> 6) << 7) | c2;
            float2 v = *(float2*)&S[row * 132 + c2];
            *(half2*)&Qh[(size_t)row * Nn + c2] =
                __halves2half2(__float2half_rn(v.x * cInv[ci]),
                               __float2half_rn(v.y * cInv[ci + 1]));
        }
    }
}

// ===========================================================================
// Softmax over n on k: fp16 in/out, uint4-vectorized, shuffle reductions
// (3 barriers instead of 16). One block (256 thr) per (b,hd) row.
// ===========================================================================
__global__ void softmax_k_kernel()
{
    int row = blockIdx.x;
    size_t base = (size_t)row * Nn;
    __shared__ float red[8];
    const int tid  = threadIdx.x;
    const int lane = tid & 31;
    const int wrp  = tid >> 5;

    uint4 u[2];
    float v[16];
    #pragma unroll
    for (int i = 0; i < 2; i++) {
        u[i] = *(const uint4*)(g_kh + base + (size_t)(tid + i * 256) * 8);
        const __half2* hp = (const __half2*)&u[i];
        #pragma unroll
        for (int j = 0; j < 4; j++) {
            float2 f = __half22float2(hp[j]);
            v[i * 8 + j * 2]     = f.x;
            v[i * 8 + j * 2 + 1] = f.y;
        }
    }
    float mx = -INFINITY;
    #pragma unroll
    for (int i = 0; i < 16; i++) mx = fmaxf(mx, v[i]);
    #pragma unroll
    for (int o = 16; o; o >>= 1) mx = fmaxf(mx, __shfl_xor_sync(0xffffffffu, mx, o));
    if (lane == 0) red[wrp] = mx;
    __syncthreads();
    mx = red[0];
    #pragma unroll
    for (int i = 1; i < 8; i++) mx = fmaxf(mx, red[i]);
    __syncthreads();                     // before red reuse

    float sum = 0.f;
    #pragma unroll
    for (int i = 0; i < 16; i++) { v[i] = __expf(v[i] - mx); sum += v[i]; }
    #pragma unroll
    for (int o = 16; o; o >>= 1) sum += __shfl_xor_sync(0xffffffffu, sum, o);
    if (lane == 0) red[wrp] = sum;
    __syncthreads();
    sum = 0.f;
    #pragma unroll
    for (int i = 0; i < 8; i++) sum += red[i];
    float inv = 1.f / sum;

    #pragma unroll
    for (int i = 0; i < 2; i++) {
        __half2* hp = (__half2*)&u[i];
        #pragma unroll
        for (int j = 0; j < 4; j++)
            hp[j] = __floats2half2_rn(v[i * 8 + j * 2] * inv, v[i * 8 + j * 2 + 1] * inv);
        *(uint4*)(g_kh + base + (size_t)(tid + i * 256) * 8) = u[i];
    }
}

// ===========================================================================
// Context partials (16 n-chunks of 256): ctxp[bh][p][d][e] = sum k[d,n]v[e,n]
// fp16 x fp16 -> fp32, A-fragments hoisted.
// ===========================================================================
#define PK_B 272
#define CT_B (64 * PK_B)
#define CTX_SMEM_BYTES (2 * CT_B)     // 34816: kH, vH

__global__ void __launch_bounds__(128, 4)
context_part()
{
    extern __shared__ char smem[];
    const uint32_t sb = smem_u32(smem);
    int bh = blockIdx.x;
    int p  = blockIdx.y;
    int b = bh >> 2, h = bh & 3;
    const __half* Kh = g_kh + ((size_t)b * HID + h * Dd) * Nn;
    const __half* Vh = g_vh + ((size_t)b * HID + h * Dd) * Nn;

    const int tid  = threadIdx.x;
    const int wid  = tid >> 5;
    const int lane = tid & 31;
    const int wm = (wid >> 1) * 32;
    const int wn = (wid & 1) * 32;

    float acc[2][4][4];
    #pragma unroll
    for (int i = 0; i < 2; i++)
        #pragma unroll
        for (int j = 0; j < 4; j++)
            #pragma unroll
            for (int r = 0; r < 4; r++) acc[i][j][r] = 0.f;

    const int lr = lane & 15;
    const int lc = (lane >> 4) & 1;
    const uint32_t kHb = sb;
    const uint32_t vHb = kHb + CT_B;

    #pragma unroll 1
    for (int sl = 0; sl < 2; sl++) {
        const int nn = p * 256 + sl * 128;
        __syncthreads();
        #pragma unroll
        for (int q = 0; q < 8; q++) {
            int id = tid + q * 128;
            int row = id >> 4, ch = id & 15;
            size_t go = (size_t)row * Nn + nn + ch * 8;
            uint32_t off = row * PK_B + ch * 16;
            CP_ASYNC16(kHb + off, Kh + go);
            CP_ASYNC16(vHb + off, Vh + go);
        }
        CP_COMMIT();
        CP_WAIT(0);
        __syncthreads();

        #pragma unroll
        for (int ks = 0; ks < 8; ks++) {
            uint32_t bhf[2][4];
            #pragma unroll
            for (int fnp = 0; fnp < 2; fnp++) {
                uint32_t off = (uint32_t)(wn + fnp * 16 + lc * 8 + (lane & 7)) * PK_B
                             + (uint32_t)(ks * 32 + ((lane >> 3) & 1) * 16);
                LDM_X4(bhf[fnp], vHb + off);
            }
            uint32_t ah[2][4];
            #pragma unroll
            for (int fm = 0; fm < 2; fm++) {
                uint32_t off = (uint32_t)(wm + fm * 16 + lr) * PK_B
                             + (uint32_t)(ks * 32 + lc * 16);
                LDM_X4(ah[fm], kHb + off);
            }
            #pragma unroll
            for (int fm = 0; fm < 2; fm++)
                #pragma unroll
                for (int fn = 0; fn < 4; fn++)
                    mma16(acc[fm][fn], ah[fm], &bhf[fn >> 1][(fn & 1) * 2]);
        }
    }

    float* dst = g_ctxp + ((size_t)bh * 16 + p) * (Dd * Dd);
    #pragma unroll
    for (int fm = 0; fm < 2; fm++) {
        int d0 = wm + fm * 16 + (lane >> 2);
        #pragma unroll
        for (int fn = 0; fn < 4; fn++) {
            int e0 = wn + fn * 8 + (lane & 3) * 2;
            dst[d0 * Dd + e0]           = acc[fm][fn][0];
            dst[d0 * Dd + e0 + 1]       = acc[fm][fn][1];
            dst[(d0 + 8) * Dd + e0]     = acc[fm][fn][2];
            dst[(d0 + 8) * Dd + e0 + 1] = acc[fm][fn][3];
        }
    }
}

// ===========================================================================
// W2[b][c][h*64+d] = sum_e w_out[c][h*64+e] * ctx[bh][d][e]; fp16 out.
// ===========================================================================
__global__ void w2_kernel(const float* __restrict__ w_out)
{
    int bh = blockIdx.x;
    int b = bh >> 2, h = bh & 3;
    __shared__ float ctx[Dd * Dd];
    const int tid = threadIdx.x;

    for (int i = tid; i < Dd * Dd; i += 256) {
        float s = 0.f;
        #pragma unroll
        for (int p = 0; p < 16; p++)
            s += g_ctxp[((size_t)bh * 16 + p) * (Dd * Dd) + i];
        ctx[i] = s;
    }
    __syncthreads();

    int c = tid;
    float w[Dd];
    #pragma unroll
    for (int e = 0; e < Dd; e++) w[e] = w_out[c * HID + h * Dd + e];
    #pragma unroll 4
    for (int d = 0; d < Dd; d++) {
        float s = 0.f;
        #pragma unroll
        for (int e = 0; e < Dd; e++) s = fmaf(w[e], ctx[d * Dd + e], s);
        g_w2h[((size_t)b * HID + c) * HID + h * Dd + d] = __float2half_rn(s);
    }
}

// ===========================================================================
extern "C" void kernel_launch(void* const* d_in, const int* in_sizes, int n_in,
                              void* d_out, int out_size)
{
    const float* x     = (const float*)d_in[0];
    const float* w_qkv = (const float*)d_in[1];
    const float* w_out = (const float*)d_in[2];
    const float* b_out = (const float*)d_in[3];
    float* out = (float*)d_out;

    __half *xh, *wh, *qh, *w2h;
    cudaGetSymbolAddress((void**)&xh, g_xh);
    cudaGetSymbolAddress((void**)&wh, g_wh);
    cudaGetSymbolAddress((void**)&qh, g_qh);
    cudaGetSymbolAddress((void**)&w2h, g_w2h);

    static int init_done = 0;
    if (!init_done) {
        cudaFuncSetAttribute(fused_gemm, cudaFuncAttributeMaxDynamicSharedMemorySize, FG_SMEM);
        cudaFuncSetAttribute(context_part, cudaFuncAttributeMaxDynamicSharedMemorySize, CTX_SMEM_BYTES);
        init_done = 1;
    }

    // 0) x, w_qkv -> fp16
    {
        int n4 = (Bn * Cc * Nn) / 4;
        half_kernel<<<(n4 + 255) / 256, 256>>>(x, xh, n4);
        int w4 = (O3 * Cc) / 4;
        half_kernel<<<(w4 + 255) / 256, 256>>>(w_qkv, wh, w4);
    }
    // 1) GEMM1: single launch, y selects q/k/v epilogue
    {
        dim3 grid(Nn / 128, O3 / 128, Bn);
        fused_gemm<<<grid, 256, FG_SMEM>>>(wh, 0, xh, (size_t)Cc * Nn,
                                           0, nullptr, nullptr);
    }
    // 2) softmax over n on k (in place, fp16)
    softmax_k_kernel<<<Bn * HID, 256>>>();
    // 3) context partials
    {
        dim3 gridc(Bn * Hh, 16);
        context_part<<<gridc, 128, CTX_SMEM_BYTES>>>();
    }
    // 4) W2
    w2_kernel<<<Bn * Hh, 256>>>(w_out);
    // 5) GEMM2: out = W2 @ q + bias
    {
        dim3 grid2(Nn / 128, HID / 128, Bn);
        fused_gemm<<<grid2, 256, FG_SMEM>>>(w2h, (size_t)HID * HID,
                                            qh, (size_t)HID * Nn,
                                            1, b_out, out);
    }
}